// round 9
// baseline (speedup 1.0000x reference)
#include <cuda_runtime.h>
#include <cuda_bf16.h>
#include <cuda_fp16.h>
#include <math.h>
#include <stdint.h>

#define SEQ    2048
#define BATCH  2
#define MTOK   4096      // BATCH*SEQ
#define DM     1024
#define NH     16
#define DHEAD  64
#define NEGV   -1000000000.0f

// -------- scratch (device globals; no allocation allowed) --------
__device__ float g_xln[MTOK * DM];          // LN1 out fp32
__device__ float g_xs [MTOK * DM];          // LN1 out bf16 split
__device__ float g_ies[MTOK * DM];          // input_embedding bf16 split
__device__ float g_qb [MTOK * DM];          // Q2 fp16 split
__device__ float g_qkv[13u << 20];          // fused QKV1 out fp16 split [M][3072]
__device__ float g_kv2[9u << 20];           // fused K2V2 out fp16 split [M][2048]
__device__ float g_ab [MTOK * DM];          // attn out bf16 split
__device__ float g_hb [MTOK * DM];
__device__ float g_rb [MTOK * DM];
__device__ float g_zb [MTOK * DM];          // LN2/LN3 out fp32
__device__ float g_zs [MTOK * DM];          // LN2/LN3 out bf16 split
__device__ float g_tb [MTOK * 4 * DM];      // MLP mid bf16 split
__device__ float g_wt [20u << 20];          // transposed weights bf16 split
__device__ float g_bias[8192];              // concat biases: [0]=qkv1(3072), [4096]=kv2(2048)

#define WT_QKV1 (0u)          // [3072][1024] hi+lo
#define WT_O1   (4u << 20)    // [1024][1024]
#define WT_Q2   (5u << 20)
#define WT_KV2  (6u << 20)    // [2048][1024]
#define WT_O2   (9u << 20)
#define WT_M1   (10u << 20)   // [4096][1024]
#define WT_M2   (14u << 20)   // [1024][4096]

// ============================================================
// helpers
// ============================================================
__device__ __forceinline__ uint32_t smem_u32(const void* p) {
    uint32_t a;
    asm("{ .reg .u64 t; cvta.to.shared.u64 t, %1; cvt.u32.u64 %0, t; }"
        : "=r"(a) : "l"(p));
    return a;
}

#define LDSM_X4(r0, r1, r2, r3, addr) \
    asm volatile("ldmatrix.sync.aligned.m8n8.x4.shared.b16 {%0,%1,%2,%3}, [%4];" \
                 : "=r"(r0), "=r"(r1), "=r"(r2), "=r"(r3) : "r"(addr))

#define LDSM_X4_T(r0, r1, r2, r3, addr) \
    asm volatile("ldmatrix.sync.aligned.m8n8.x4.trans.shared.b16 {%0,%1,%2,%3}, [%4];" \
                 : "=r"(r0), "=r"(r1), "=r"(r2), "=r"(r3) : "r"(addr))

#define MMA_BF16(c, a, b0, b1) \
    asm volatile("mma.sync.aligned.m16n8k16.row.col.f32.bf16.bf16.f32 " \
                 "{%0,%1,%2,%3}, {%4,%5,%6,%7}, {%8,%9}, {%0,%1,%2,%3};" \
                 : "+f"((c)[0]), "+f"((c)[1]), "+f"((c)[2]), "+f"((c)[3]) \
                 : "r"((a)[0]), "r"((a)[1]), "r"((a)[2]), "r"((a)[3]), \
                   "r"(b0), "r"(b1))

#define MMA_F16(c, a, b0, b1) \
    asm volatile("mma.sync.aligned.m16n8k16.row.col.f32.f16.f16.f32 " \
                 "{%0,%1,%2,%3}, {%4,%5,%6,%7}, {%8,%9}, {%0,%1,%2,%3};" \
                 : "+f"((c)[0]), "+f"((c)[1]), "+f"((c)[2]), "+f"((c)[3]) \
                 : "r"((a)[0]), "r"((a)[1]), "r"((a)[2]), "r"((a)[3]), \
                   "r"(b0), "r"(b1))

#define CP_ASYNC16(dst, src) \
    asm volatile("cp.async.cg.shared.global [%0], [%1], 16;" \
                 :: "r"(dst), "l"(src) : "memory")
#define CP_COMMIT  asm volatile("cp.async.commit_group;" ::: "memory")
#define CP_WAIT0   asm volatile("cp.async.wait_group 0;" ::: "memory")

__device__ __forceinline__ uint32_t pack_h2(float a, float b) {
    __half2 h; h.x = __float2half(a); h.y = __float2half(b);
    return *(uint32_t*)&h;
}
__device__ __forceinline__ void bfsplit_store(__nv_bfloat16* hp, __nv_bfloat16* lp,
                                              float a, float b) {
    __nv_bfloat162 h = __floats2bfloat162_rn(a, b);
    __nv_bfloat162 l = __floats2bfloat162_rn(a - __bfloat162float(h.x),
                                             b - __bfloat162float(h.y));
    *(uint32_t*)hp = *(uint32_t*)&h;
    *(uint32_t*)lp = *(uint32_t*)&l;
}
__device__ __forceinline__ void hsplit_store(__half* hp, __half* lp,
                                             float a, float b) {
    __half ha = __float2half(a), hb = __float2half(b);
    __half2 h; h.x = ha; h.y = hb;
    __half2 l; l.x = __float2half(a - __half2float(ha));
    l.y = __float2half(b - __half2float(hb));
    *(uint32_t*)hp = *(uint32_t*)&h;
    *(uint32_t*)lp = *(uint32_t*)&l;
}

__device__ __forceinline__ float block_sum(float v, float* red) {
    int lane = threadIdx.x & 31, w = threadIdx.x >> 5;
    #pragma unroll
    for (int o = 16; o > 0; o >>= 1) v += __shfl_xor_sync(0xffffffffu, v, o);
    __syncthreads();
    if (lane == 0) red[w] = v;
    __syncthreads();
    if (w == 0) {
        float x = (lane < 8) ? red[lane] : 0.0f;
        #pragma unroll
        for (int o = 4; o > 0; o >>= 1) x += __shfl_xor_sync(0xffffffffu, x, o);
        if (lane == 0) red[0] = x;
    }
    __syncthreads();
    return red[0];
}
__device__ __forceinline__ float gelu_exact(float x) {
    return 0.5f * x * (1.0f + erff(x * 0.7071067811865475f));
}

// -------- weight transpose + bf16 split into fused buffer --------
// W: [K][N_local] fp32.  Output rows [row0, row0+N_local) of a fused
// [Ntot][K] hi array; lo at +Ntot*K.
__global__ __launch_bounds__(256) void transpose_split_kernel(
    const float* __restrict__ W, __nv_bfloat16* __restrict__ WThi,
    int K, int N, int row0, int Ntot)
{
    __shared__ float t[32][33];
    __nv_bfloat16* WTlo = WThi + (size_t)Ntot * K;
    int n0 = blockIdx.x * 32, k0 = blockIdx.y * 32;
    int tx = threadIdx.x & 31, ty = threadIdx.x >> 5;
    #pragma unroll
    for (int i = 0; i < 4; i++)
        t[ty + 8 * i][tx] = W[(size_t)(k0 + ty + 8 * i) * N + n0 + tx];
    __syncthreads();
    #pragma unroll
    for (int i = 0; i < 4; i++) {
        float x = t[tx][ty + 8 * i];
        __nv_bfloat16 h = __float2bfloat16(x);
        __nv_bfloat16 l = __float2bfloat16(x - __bfloat162float(h));
        size_t o = (size_t)(row0 + n0 + ty + 8 * i) * K + k0 + tx;
        WThi[o] = h; WTlo[o] = l;
    }
}

// -------- plain bf16 split of an fp32 tensor --------
__global__ __launch_bounds__(256) void split_bf16_kernel(
    const float* __restrict__ X, __nv_bfloat16* __restrict__ Hi, int n)
{
    __nv_bfloat16* Lo = Hi + (size_t)n;
    int i = (blockIdx.x * 256 + threadIdx.x) * 4;
    float4 v = *(const float4*)(X + i);
    bfsplit_store(Hi + i,     Lo + i,     v.x, v.y);
    bfsplit_store(Hi + i + 2, Lo + i + 2, v.z, v.w);
}

// -------- fused embedding + LN1 (fp32 + bf16-split outs) --------
__global__ __launch_bounds__(256) void embed_ln_kernel(
    const int* __restrict__ ids, const float* __restrict__ tok,
    const float* __restrict__ pos, const float* __restrict__ gw,
    const float* __restrict__ bw, float* __restrict__ out,
    __nv_bfloat16* __restrict__ Shi)
{
    __shared__ float red[32];
    __nv_bfloat16* Slo = Shi + (size_t)MTOK * DM;
    int row = blockIdx.x;
    int s   = row & (SEQ - 1);
    int id  = ids[row];
    int d   = threadIdx.x * 4;
    float4 t4 = *(const float4*)(tok + (size_t)id * DM + d);
    float4 p4 = *(const float4*)(pos + (size_t)s  * DM + d);
    float4 v;
    v.x = t4.x + p4.x; v.y = t4.y + p4.y; v.z = t4.z + p4.z; v.w = t4.w + p4.w;
    float mu = block_sum(v.x + v.y + v.z + v.w, red) * (1.0f / DM);
    float dx = v.x - mu, dy = v.y - mu, dz = v.z - mu, dw = v.w - mu;
    float var = block_sum(dx*dx + dy*dy + dz*dz + dw*dw, red) * (1.0f / DM);
    float rstd = rsqrtf(var + 1e-5f);
    float4 o;
    o.x = dx * rstd * gw[d+0] + bw[d+0];
    o.y = dy * rstd * gw[d+1] + bw[d+1];
    o.z = dz * rstd * gw[d+2] + bw[d+2];
    o.w = dw * rstd * gw[d+3] + bw[d+3];
    size_t off = (size_t)row * DM + d;
    *(float4*)(out + off) = o;
    bfsplit_store(Shi + off,     Slo + off,     o.x, o.y);
    bfsplit_store(Shi + off + 2, Slo + off + 2, o.z, o.w);
}

// -------- plain LN (fp32 + bf16-split outs) --------
__global__ __launch_bounds__(256) void ln_kernel(
    const float* __restrict__ in, const float* __restrict__ gw,
    const float* __restrict__ bw, float* __restrict__ out,
    __nv_bfloat16* __restrict__ Shi)
{
    __shared__ float red[32];
    __nv_bfloat16* Slo = Shi + (size_t)MTOK * DM;
    int row = blockIdx.x;
    int d   = threadIdx.x * 4;
    float4 v = *(const float4*)(in + (size_t)row * DM + d);
    float mu = block_sum(v.x + v.y + v.z + v.w, red) * (1.0f / DM);
    float dx = v.x - mu, dy = v.y - mu, dz = v.z - mu, dw = v.w - mu;
    float var = block_sum(dx*dx + dy*dy + dz*dz + dw*dw, red) * (1.0f / DM);
    float rstd = rsqrtf(var + 1e-5f);
    float4 o;
    o.x = dx * rstd * gw[d+0] + bw[d+0];
    o.y = dy * rstd * gw[d+1] + bw[d+1];
    o.z = dz * rstd * gw[d+2] + bw[d+2];
    o.w = dw * rstd * gw[d+3] + bw[d+3];
    size_t off = (size_t)row * DM + d;
    *(float4*)(out + off) = o;
    bfsplit_store(Shi + off,     Slo + off,     o.x, o.y);
    bfsplit_store(Shi + off + 2, Slo + off + 2, o.z, o.w);
}

// ============================================================
// bf16x3-split GEMM, pre-split inputs, cp.async staging, 2 CTAs/SM
// C = A*W + bias.  A: bf16 split [M][K] (lo at +M*K).
// WThi: bf16 split [N][K] (lo at +N*K).
// epi: 0 fp32 | 1 gelu->bf16split | 2 fp32+R | 3 fp16split
// ============================================================
#define GTILE 10240
#define GEMM_SMEM (2 * 4 * GTILE)   // 81920

__global__ __launch_bounds__(256, 2) void gemm_bf16_kernel(
    const __nv_bfloat16* __restrict__ Ahi, const __nv_bfloat16* __restrict__ WThi,
    const float* __restrict__ bias, const float* __restrict__ R,
    float* __restrict__ C, int M, int N, int K, int epi)
{
    extern __shared__ char smem[];
    const int tid = threadIdx.x, wid = tid >> 5, lane = tid & 31;
    const int m0 = blockIdx.y * 128, n0 = blockIdx.x * 128;
    const int warpM = (wid & 3) * 32, warpN = (wid >> 2) * 64;
    const uint32_t sb = smem_u32(smem);

    const __nv_bfloat16* Alo  = Ahi  + (size_t)M * K;
    const __nv_bfloat16* WTlo = WThi + (size_t)N * K;
    const __nv_bfloat16* srcs[4] = {
        Ahi + (size_t)m0 * K,  Alo + (size_t)m0 * K,
        WThi + (size_t)n0 * K, WTlo + (size_t)n0 * K };

    float acc[2][8][4];
    #pragma unroll
    for (int i = 0; i < 2; i++)
        #pragma unroll
        for (int j = 0; j < 8; j++)
            #pragma unroll
            for (int q = 0; q < 4; q++) acc[i][j][q] = 0.0f;

    const int a_stat = (warpM + ((lane >> 3) & 1) * 8 + (lane & 7)) * 40 + (lane >> 4) * 8;
    const int b_stat = (warpN + ((lane >> 4) & 1) * 8 + (lane & 7)) * 40 + ((lane >> 3) & 1) * 8;
    const int NKB = K >> 5;

#define G_ISSUE(kb, buf) { \
    _Pragma("unroll") for (int i = 0; i < 8; i++) { \
        const int tile = i >> 1; \
        int r = ((tid >> 2) + 64 * i) & 127; \
        int s = tid & 3; \
        const __nv_bfloat16* src = srcs[tile] + (size_t)r * K + (kb) * 32 + s * 8; \
        uint32_t dst = sb + (buf) * 40960 + tile * GTILE + (uint32_t)(r * 40 + s * 8) * 2; \
        CP_ASYNC16(dst, src); \
    } \
    CP_COMMIT; }

#define G_COMPUTE(buf) { \
    uint32_t tb0 = sb + (buf) * 40960; \
    _Pragma("unroll") for (int ks = 0; ks < 2; ks++) { \
        const int Cc = ks * 16; \
        uint32_t fa[2][4], fl[2][4]; \
        _Pragma("unroll") for (int mb = 0; mb < 2; mb++) { \
            uint32_t ad = tb0 + (uint32_t)(a_stat + mb * 640 + Cc) * 2; \
            LDSM_X4(fa[mb][0], fa[mb][1], fa[mb][2], fa[mb][3], ad); \
            LDSM_X4(fl[mb][0], fl[mb][1], fl[mb][2], fl[mb][3], ad + GTILE); \
        } \
        _Pragma("unroll") for (int p = 0; p < 4; p++) { \
            uint32_t bh[4], bl[4]; \
            uint32_t bd = tb0 + 2 * GTILE + (uint32_t)(b_stat + p * 640 + Cc) * 2; \
            LDSM_X4(bh[0], bh[1], bh[2], bh[3], bd); \
            LDSM_X4(bl[0], bl[1], bl[2], bl[3], bd + GTILE); \
            _Pragma("unroll") for (int mb = 0; mb < 2; mb++) { \
                MMA_BF16(acc[mb][2*p],   fa[mb], bh[0], bh[1]); \
                MMA_BF16(acc[mb][2*p],   fa[mb], bl[0], bl[1]); \
                MMA_BF16(acc[mb][2*p],   fl[mb], bh[0], bh[1]); \
                MMA_BF16(acc[mb][2*p+1], fa[mb], bh[2], bh[3]); \
                MMA_BF16(acc[mb][2*p+1], fa[mb], bl[2], bl[3]); \
                MMA_BF16(acc[mb][2*p+1], fl[mb], bh[2], bh[3]); \
            } } } }

    G_ISSUE(0, 0);
    CP_WAIT0;
    __syncthreads();

    for (int kb = 0; kb < NKB; kb++) {
        if (kb + 1 < NKB) G_ISSUE(kb + 1, (kb + 1) & 1);
        G_COMPUTE(kb & 1);
        if (kb + 1 < NKB) {
            CP_WAIT0;
            __syncthreads();
        }
    }

    // epilogue
    const int g = lane >> 2, t = lane & 3;
    #pragma unroll
    for (int mb = 0; mb < 2; mb++)
        #pragma unroll
        for (int nb = 0; nb < 8; nb++) {
            int row = m0 + warpM + mb * 16 + g;
            int col = n0 + warpN + nb * 8 + 2 * t;
            float2 b2 = *(const float2*)(bias + col);
            float v0 = acc[mb][nb][0] + b2.x, v1 = acc[mb][nb][1] + b2.y;
            float v2 = acc[mb][nb][2] + b2.x, v3 = acc[mb][nb][3] + b2.y;
            size_t o0 = (size_t)row * N + col, o1 = (size_t)(row + 8) * N + col;
            if (epi == 0 || epi == 2) {
                if (epi == 2) {
                    float2 r0 = *(const float2*)(R + o0);
                    float2 r1 = *(const float2*)(R + o1);
                    v0 += r0.x; v1 += r0.y; v2 += r1.x; v3 += r1.y;
                }
                float2 c0 = {v0, v1}, c1 = {v2, v3};
                *(float2*)(C + o0) = c0;
                *(float2*)(C + o1) = c1;
            } else if (epi == 1) {
                v0 = gelu_exact(v0); v1 = gelu_exact(v1);
                v2 = gelu_exact(v2); v3 = gelu_exact(v3);
                __nv_bfloat16* Chi = (__nv_bfloat16*)C;
                __nv_bfloat16* Clo = Chi + (size_t)M * N;
                bfsplit_store(Chi + o0, Clo + o0, v0, v1);
                bfsplit_store(Chi + o1, Clo + o1, v2, v3);
            } else {
                __half* Chi = (__half*)C;
                __half* Clo = Chi + (size_t)M * N;
                hsplit_store(Chi + o0, Clo + o0, v0, v1);
                hsplit_store(Chi + o1, Clo + o1, v2, v3);
            }
        }
}

// ============================================================
// flash attention, pre-split fp16 Q/K (x3), fp16 V (hi plane)
// strided Q/K/V so tensors can live in fused GEMM outputs
// ============================================================
#define FS 72
#define FK_LO 9216
#define FV    18432
#define FBUF  27648
#define FLASH_SMEM (2 * FBUF + 512)

__global__ __launch_bounds__(128) void flash_mma_kernel(
    const __half* __restrict__ Qhi, int qs,
    const __half* __restrict__ Khi, const __half* __restrict__ Vhi, int ks,
    const int* __restrict__ ids, __nv_bfloat16* __restrict__ Ohi, int causal)
{
    extern __shared__ char fsm[];
    const uint32_t sb = smem_u32(fsm);
    float* nadd = (float*)(fsm + 2 * FBUF);

    const int tid = threadIdx.x, wid = tid >> 5, lane = tid & 31;
    const int qt = blockIdx.x, h = blockIdx.y, b = blockIdx.z;
    const int qbase = qt * 64;
    const int g = lane >> 2, t = lane & 3;

    const __half* Qlo = Qhi + (size_t)MTOK * qs;
    const __half* Klo = Khi + (size_t)MTOK * ks;
    __nv_bfloat16* Olo = Ohi + (size_t)MTOK * DM;

    const __half* Qph = Qhi + (size_t)b * SEQ * qs + h * DHEAD;
    const __half* Qpl = Qlo + (size_t)b * SEQ * qs + h * DHEAD;
    const __half* Kph = Khi + (size_t)b * SEQ * ks + h * DHEAD;
    const __half* Kpl = Klo + (size_t)b * SEQ * ks + h * DHEAD;
    const __half* Vp  = Vhi + (size_t)b * SEQ * ks + h * DHEAD;

#define F_STAGE(kbase, bufbase, nbuf) { \
    _Pragma("unroll") for (int i = 0; i < 8; i++) { \
        const int arr = i >> 2; \
        int r = (16 * i + (tid >> 3)) & 63; \
        int s = tid & 7; \
        const __half* src = (arr ? Kpl : Kph) + (size_t)((kbase) + r) * ks + s * 8; \
        uint32_t dst = sb + (bufbase) + arr * FK_LO + (uint32_t)(r * FS + s * 8) * 2; \
        CP_ASYNC16(dst, src); \
    } \
    _Pragma("unroll") for (int i = 0; i < 4; i++) { \
        int r = (16 * i + (tid >> 3)) & 63; \
        int s = tid & 7; \
        const __half* src = Vp + (size_t)((kbase) + r) * ks + s * 8; \
        uint32_t dst = sb + (bufbase) + FV + (uint32_t)(r * FS + s * 8) * 2; \
        CP_ASYNC16(dst, src); \
    } \
    if (tid < 64) \
        nadd[(nbuf) * 64 + tid] = (ids[b * SEQ + (kbase) + tid] == 0) ? NEGV : 0.0f; \
    CP_COMMIT; }

    // ---- stage Q into buf1 region, K/V tile 0 into buf0 ----
    #pragma unroll
    for (int i = 0; i < 8; i++) {
        const int arr = i >> 2;
        int r = (16 * i + (tid >> 3)) & 63;
        int s = tid & 7;
        const __half* src = (arr ? Qpl : Qph) + (size_t)(qbase + r) * qs + s * 8;
        uint32_t dst = sb + FBUF + arr * FK_LO + (uint32_t)(r * FS + s * 8) * 2;
        CP_ASYNC16(dst, src);
    }
    CP_COMMIT;
    F_STAGE(0, 0, 0);
    CP_WAIT0;
    __syncthreads();

    // ---- Q fragments from buf1 ----
    uint32_t qh[4][4], ql[4][4];
    {
        int arow = (lane & 15) + 16 * wid;
        int acb  = ((lane >> 4) & 1) * 8;
        #pragma unroll
        for (int kk = 0; kk < 4; kk++) {
            uint32_t ad = sb + FBUF + (uint32_t)(arow * FS + acb + kk * 16) * 2;
            LDSM_X4(qh[kk][0], qh[kk][1], qh[kk][2], qh[kk][3], ad);
            LDSM_X4(ql[kk][0], ql[kk][1], ql[kk][2], ql[kk][3], ad + FK_LO);
        }
    }

    float mA = -3.0e38f, mB = -3.0e38f, lA = 0.0f, lB = 0.0f;
    float O[8][4];
    #pragma unroll
    for (int nb = 0; nb < 8; nb++)
        #pragma unroll
        for (int q = 0; q < 4; q++) O[nb][q] = 0.0f;

    const int rowA = qbase + 16 * wid + g;
    const int nkt = causal ? (qt + 1) : (SEQ / 64);

    for (int kt = 0; kt < nkt; kt++) {
        const int cur = kt & 1;
        const uint32_t cb = sb + cur * FBUF;
        const bool diag = causal && (kt == qt);
        CP_WAIT0;
        __syncthreads();

        // ---- S = Q K^T (fp16x3) ----
        float sc[8][4];
        #pragma unroll
        for (int nb = 0; nb < 8; nb++)
            #pragma unroll
            for (int q = 0; q < 4; q++) sc[nb][q] = 0.0f;

        #pragma unroll
        for (int kk = 0; kk < 4; kk++) {
            #pragma unroll
            for (int p = 0; p < 4; p++) {
                int brow = p * 16 + ((lane >> 4) & 1) * 8 + (lane & 7);
                int bcol = kk * 16 + ((lane >> 3) & 1) * 8;
                uint32_t bd = cb + (uint32_t)(brow * FS + bcol) * 2;
                uint32_t bh[4], bl[4];
                LDSM_X4(bh[0], bh[1], bh[2], bh[3], bd);
                LDSM_X4(bl[0], bl[1], bl[2], bl[3], bd + FK_LO);
                MMA_F16(sc[2*p],   qh[kk], bh[0], bh[1]);
                MMA_F16(sc[2*p],   qh[kk], bl[0], bl[1]);
                MMA_F16(sc[2*p],   ql[kk], bh[0], bh[1]);
                MMA_F16(sc[2*p+1], qh[kk], bh[2], bh[3]);
                MMA_F16(sc[2*p+1], qh[kk], bl[2], bl[3]);
                MMA_F16(sc[2*p+1], ql[kk], bh[2], bh[3]);
            }
        }

        // ---- prefetch next tile (overlaps softmax + PV) ----
        if (kt + 1 < nkt)
            F_STAGE((kt + 1) * 64, (1 - cur) * FBUF, 1 - cur);

        // ---- scale + masks + online softmax ----
        const int kbase = kt * 64;
        float rmaxA = -3.0e38f, rmaxB = -3.0e38f;
        #pragma unroll
        for (int nb = 0; nb < 8; nb++) {
            int col0 = kbase + nb * 8 + 2 * t;
            float p0 = nadd[cur * 64 + nb * 8 + 2 * t];
            float p1 = nadd[cur * 64 + nb * 8 + 2 * t + 1];
            float v0 = sc[nb][0] * 0.125f + p0;
            float v1 = sc[nb][1] * 0.125f + p1;
            float v2 = sc[nb][2] * 0.125f + p0;
            float v3 = sc[nb][3] * 0.125f + p1;
            if (diag) {
                if (col0     > rowA)     v0 += NEGV;
                if (col0 + 1 > rowA)     v1 += NEGV;
                if (col0     > rowA + 8) v2 += NEGV;
                if (col0 + 1 > rowA + 8) v3 += NEGV;
            }
            sc[nb][0] = v0; sc[nb][1] = v1; sc[nb][2] = v2; sc[nb][3] = v3;
            rmaxA = fmaxf(rmaxA, fmaxf(v0, v1));
            rmaxB = fmaxf(rmaxB, fmaxf(v2, v3));
        }
        #pragma unroll
        for (int o = 1; o <= 2; o <<= 1) {
            rmaxA = fmaxf(rmaxA, __shfl_xor_sync(0xffffffffu, rmaxA, o));
            rmaxB = fmaxf(rmaxB, __shfl_xor_sync(0xffffffffu, rmaxB, o));
        }
        float mnA = fmaxf(mA, rmaxA), mnB = fmaxf(mB, rmaxB);
        float aA = __expf(mA - mnA), aB = __expf(mB - mnB);
        mA = mnA; mB = mnB;

        uint32_t af[4][4];
        float sA = 0.0f, sB = 0.0f;
        #pragma unroll
        for (int nb = 0; nb < 8; nb++) {
            float p0 = __expf(sc[nb][0] - mnA);
            float p1 = __expf(sc[nb][1] - mnA);
            float p2 = __expf(sc[nb][2] - mnB);
            float p3 = __expf(sc[nb][3] - mnB);
            __half h0 = __float2half(p0), h1 = __float2half(p1);
            __half h2 = __float2half(p2), h3 = __float2half(p3);
            sA += __half2float(h0) + __half2float(h1);
            sB += __half2float(h2) + __half2float(h3);
            __half2 u01; u01.x = h0; u01.y = h1;
            __half2 u23; u23.x = h2; u23.y = h3;
            int kk = nb >> 1, hi = nb & 1;
            af[kk][hi * 2 + 0] = *(uint32_t*)&u01;
            af[kk][hi * 2 + 1] = *(uint32_t*)&u23;
        }
        #pragma unroll
        for (int o = 1; o <= 2; o <<= 1) {
            sA += __shfl_xor_sync(0xffffffffu, sA, o);
            sB += __shfl_xor_sync(0xffffffffu, sB, o);
        }
        lA = lA * aA + sA; lB = lB * aB + sB;
        #pragma unroll
        for (int nb = 0; nb < 8; nb++) {
            O[nb][0] *= aA; O[nb][1] *= aA;
            O[nb][2] *= aB; O[nb][3] *= aB;
        }

        // ---- O += P V ----
        #pragma unroll
        for (int kk = 0; kk < 4; kk++) {
            #pragma unroll
            for (int nbp = 0; nbp < 4; nbp++) {
                int vrow = kk * 16 + (lane & 15);
                int vcol = nbp * 16 + (lane >> 4) * 8;
                uint32_t bd = cb + FV + (uint32_t)(vrow * FS + vcol) * 2;
                uint32_t v0, v1, v2, v3;
                LDSM_X4_T(v0, v1, v2, v3, bd);
                MMA_F16(O[2*nbp],     af[kk], v0, v1);
                MMA_F16(O[2*nbp + 1], af[kk], v2, v3);
            }
        }
    }

    // ---- write out (bf16 split for next GEMM's A) ----
    float iA = 1.0f / lA, iB = 1.0f / lB;
    #pragma unroll
    for (int nb = 0; nb < 8; nb++) {
        int col = h * DHEAD + nb * 8 + 2 * t;
        size_t off0 = ((size_t)b * SEQ + rowA) * DM + col;
        size_t off1 = ((size_t)b * SEQ + rowA + 8) * DM + col;
        bfsplit_store(Ohi + off0, Olo + off0, O[nb][0] * iA, O[nb][1] * iA);
        bfsplit_store(Ohi + off1, Olo + off1, O[nb][2] * iB, O[nb][3] * iB);
    }
}

// ============================================================
// host pipeline
// ============================================================
extern "C" void kernel_launch(void* const* d_in, const int* in_sizes, int n_in,
                              void* d_out, int out_size)
{
    const float* input_embedding = (const float*)d_in[0];
    const int*   input_ids       = (const int*)  d_in[1];
    const int*   target_ids      = (const int*)  d_in[2];
    const float* tok_emb = (const float*)d_in[3];
    const float* pos_emb = (const float*)d_in[4];
    const float* ln1_g = (const float*)d_in[5],  *ln1_b = (const float*)d_in[6];
    const float* q1_w  = (const float*)d_in[7],  *q1_b  = (const float*)d_in[8];
    const float* k1_w  = (const float*)d_in[9],  *k1_b  = (const float*)d_in[10];
    const float* v1_w  = (const float*)d_in[11], *v1_b  = (const float*)d_in[12];
    const float* out1_w= (const float*)d_in[13], *out1_b= (const float*)d_in[14];
    const float* ln2_g = (const float*)d_in[15], *ln2_b = (const float*)d_in[16];
    const float* q2_w  = (const float*)d_in[17], *q2_b  = (const float*)d_in[18];
    const float* k2_w  = (const float*)d_in[19], *k2_b  = (const float*)d_in[20];
    const float* v2_w  = (const float*)d_in[21], *v2_b  = (const float*)d_in[22];
    const float* out2_w= (const float*)d_in[23], *out2_b= (const float*)d_in[24];
    const float* ln3_g = (const float*)d_in[25], *ln3_b = (const float*)d_in[26];
    const float* mlp_w1= (const float*)d_in[27], *mlp_b1= (const float*)d_in[28];
    const float* mlp_w2= (const float*)d_in[29], *mlp_b2= (const float*)d_in[30];

    float *xln, *xs, *ies, *qb, *qkv, *kv2, *ab, *hb, *rb, *zb, *zs, *tb, *wt, *gbias;
    cudaGetSymbolAddress((void**)&xln, g_xln);
    cudaGetSymbolAddress((void**)&xs,  g_xs);
    cudaGetSymbolAddress((void**)&ies, g_ies);
    cudaGetSymbolAddress((void**)&qb,  g_qb);
    cudaGetSymbolAddress((void**)&qkv, g_qkv);
    cudaGetSymbolAddress((void**)&kv2, g_kv2);
    cudaGetSymbolAddress((void**)&ab,  g_ab);
    cudaGetSymbolAddress((void**)&hb,  g_hb);
    cudaGetSymbolAddress((void**)&rb,  g_rb);
    cudaGetSymbolAddress((void**)&zb,  g_zb);
    cudaGetSymbolAddress((void**)&zs,  g_zs);
    cudaGetSymbolAddress((void**)&tb,  g_tb);
    cudaGetSymbolAddress((void**)&wt,  g_wt);
    cudaGetSymbolAddress((void**)&gbias, g_bias);

    cudaFuncSetAttribute(gemm_bf16_kernel,
                         cudaFuncAttributeMaxDynamicSharedMemorySize, GEMM_SMEM);
    cudaFuncSetAttribute(flash_mma_kernel,
                         cudaFuncAttributeMaxDynamicSharedMemorySize, FLASH_SMEM);

    // ---- one-time prep ----
    {
        dim3 g1(DM / 32, DM / 32);
        // fused QKV1 weights [3072][1024]
        transpose_split_kernel<<<g1, 256>>>(q1_w, (__nv_bfloat16*)(wt + WT_QKV1), DM, DM, 0,    3 * DM);
        transpose_split_kernel<<<g1, 256>>>(k1_w, (__nv_bfloat16*)(wt + WT_QKV1), DM, DM, 1024, 3 * DM);
        transpose_split_kernel<<<g1, 256>>>(v1_w, (__nv_bfloat16*)(wt + WT_QKV1), DM, DM, 2048, 3 * DM);
        transpose_split_kernel<<<g1, 256>>>(out1_w,(__nv_bfloat16*)(wt + WT_O1),  DM, DM, 0, DM);
        transpose_split_kernel<<<g1, 256>>>(q2_w, (__nv_bfloat16*)(wt + WT_Q2),   DM, DM, 0, DM);
        // fused K2V2 weights [2048][1024]
        transpose_split_kernel<<<g1, 256>>>(k2_w, (__nv_bfloat16*)(wt + WT_KV2),  DM, DM, 0,    2 * DM);
        transpose_split_kernel<<<g1, 256>>>(v2_w, (__nv_bfloat16*)(wt + WT_KV2),  DM, DM, 1024, 2 * DM);
        transpose_split_kernel<<<g1, 256>>>(out2_w,(__nv_bfloat16*)(wt + WT_O2),  DM, DM, 0, DM);
        dim3 gm1(4 * DM / 32, DM / 32);
        transpose_split_kernel<<<gm1, 256>>>(mlp_w1, (__nv_bfloat16*)(wt + WT_M1), DM, 4 * DM, 0, 4 * DM);
        dim3 gm2(DM / 32, 4 * DM / 32);
        transpose_split_kernel<<<gm2, 256>>>(mlp_w2, (__nv_bfloat16*)(wt + WT_M2), 4 * DM, DM, 0, DM);
        split_bf16_kernel<<<MTOK * DM / 1024, 256>>>(input_embedding,
                                                     (__nv_bfloat16*)ies, MTOK * DM);
        // concat biases (D2D async copies are graph-capturable)
        cudaMemcpyAsync(gbias,        q1_b, DM * 4, cudaMemcpyDeviceToDevice);
        cudaMemcpyAsync(gbias + 1024, k1_b, DM * 4, cudaMemcpyDeviceToDevice);
        cudaMemcpyAsync(gbias + 2048, v1_b, DM * 4, cudaMemcpyDeviceToDevice);
        cudaMemcpyAsync(gbias + 4096, k2_b, DM * 4, cudaMemcpyDeviceToDevice);
        cudaMemcpyAsync(gbias + 5120, v2_b, DM * 4, cudaMemcpyDeviceToDevice);
    }

    dim3 gN1(DM / 128, MTOK / 128);          // (8, 32)
    dim3 gN3(3 * DM / 128, MTOK / 128);      // (24, 32) fused QKV
    dim3 gN2(2 * DM / 128, MTOK / 128);      // (16, 32) fused KV2
    dim3 gN4(4 * DM / 128, MTOK / 128);      // (32, 32)
    dim3 gF(SEQ / 64, NH, BATCH);

    // x = LN1(tok_emb[tgt] + pos)
    embed_ln_kernel<<<MTOK, 256>>>(target_ids, tok_emb, pos_emb, ln1_g, ln1_b,
                                   xln, (__nv_bfloat16*)xs);

    // self-attention: fused QKV GEMM -> flash -> out-proj
    gemm_bf16_kernel<<<gN3, 256, GEMM_SMEM>>>((const __nv_bfloat16*)xs,
        (const __nv_bfloat16*)(wt + WT_QKV1), gbias, nullptr, qkv, MTOK, 3 * DM, DM, 3);
    flash_mma_kernel<<<gF, 128, FLASH_SMEM>>>((const __half*)qkv, 3 * DM,
        (const __half*)qkv + 1024, (const __half*)qkv + 2048, 3 * DM,
        target_ids, (__nv_bfloat16*)ab, 1);
    gemm_bf16_kernel<<<gN1, 256, GEMM_SMEM>>>((const __nv_bfloat16*)ab,
        (const __nv_bfloat16*)(wt + WT_O1), out1_b, xln, hb, MTOK, DM, DM, 2);

    // cross-attention (residual uses LN2 output, matching reference)
    ln_kernel<<<MTOK, 256>>>(hb, ln2_g, ln2_b, zb, (__nv_bfloat16*)zs);
    gemm_bf16_kernel<<<gN1, 256, GEMM_SMEM>>>((const __nv_bfloat16*)zs,
        (const __nv_bfloat16*)(wt + WT_Q2), q2_b, nullptr, qb, MTOK, DM, DM, 3);
    gemm_bf16_kernel<<<gN2, 256, GEMM_SMEM>>>((const __nv_bfloat16*)ies,
        (const __nv_bfloat16*)(wt + WT_KV2), gbias + 4096, nullptr, kv2, MTOK, 2 * DM, DM, 3);
    flash_mma_kernel<<<gF, 128, FLASH_SMEM>>>((const __half*)qb, DM,
        (const __half*)kv2, (const __half*)kv2 + 1024, 2 * DM,
        input_ids, (__nv_bfloat16*)ab, 0);
    gemm_bf16_kernel<<<gN1, 256, GEMM_SMEM>>>((const __nv_bfloat16*)ab,
        (const __nv_bfloat16*)(wt + WT_O2), out2_b, zb, rb, MTOK, DM, DM, 2);

    // MLP
    ln_kernel<<<MTOK, 256>>>(rb, ln3_g, ln3_b, zb, (__nv_bfloat16*)zs);
    gemm_bf16_kernel<<<gN4, 256, GEMM_SMEM>>>((const __nv_bfloat16*)zs,
        (const __nv_bfloat16*)(wt + WT_M1), mlp_b1, nullptr, tb, MTOK, 4 * DM, DM, 1);
    gemm_bf16_kernel<<<gN1, 256, GEMM_SMEM>>>((const __nv_bfloat16*)tb,
        (const __nv_bfloat16*)(wt + WT_M2), mlp_b2, rb, (float*)d_out, MTOK, DM, 4 * DM, 2);
}

// round 12
// speedup vs baseline: 1.2813x; 1.2813x over previous
#include <cuda_runtime.h>
#include <cuda_bf16.h>
#include <cuda_fp16.h>
#include <math.h>
#include <stdint.h>

#define SEQ    2048
#define BATCH  2
#define MTOK   4096      // BATCH*SEQ
#define DM     1024
#define NH     16
#define DHEAD  64
#define NEGV   -1000000000.0f

// -------- scratch (device globals; no allocation allowed) --------
__device__ float g_xln[MTOK * DM];          // LN1 out fp32
__device__ float g_xs [MTOK * DM];          // LN1 out fp16 split
__device__ float g_ies[MTOK * DM];          // input_embedding fp16 split
__device__ float g_qb [MTOK * DM];          // Q2 fp16 split
__device__ float g_qkv[13u << 20];          // fused QKV1 out fp16 split [M][3072]
__device__ float g_kv2[9u << 20];           // fused K2V2 out fp16 split [M][2048]
__device__ float g_ab [MTOK * DM];          // attn out fp16 split
__device__ float g_hb [MTOK * DM];
__device__ float g_rb [MTOK * DM];
__device__ float g_zb [MTOK * DM];          // LN2/LN3 out fp32
__device__ float g_zs [MTOK * DM];          // LN2/LN3 out fp16 split
__device__ float g_tb [MTOK * 4 * DM];      // MLP mid fp16 split
__device__ float g_wt [20u << 20];          // transposed weights fp16 [N][K]
__device__ float g_bias[8192];              // concat biases

#define WT_QKV1 (0u)          // [3072][1024] fp16
#define WT_O1   (2u << 20)
#define WT_Q2   (3u << 20)
#define WT_KV2  (4u << 20)    // [2048][1024]
#define WT_O2   (6u << 20)
#define WT_M1   (7u << 20)    // [4096][1024]
#define WT_M2   (9u << 20)    // [1024][4096]

// ============================================================
// helpers
// ============================================================
__device__ __forceinline__ uint32_t smem_u32(const void* p) {
    uint32_t a;
    asm("{ .reg .u64 t; cvta.to.shared.u64 t, %1; cvt.u32.u64 %0, t; }"
        : "=r"(a) : "l"(p));
    return a;
}

#define LDSM_X4(r0, r1, r2, r3, addr) \
    asm volatile("ldmatrix.sync.aligned.m8n8.x4.shared.b16 {%0,%1,%2,%3}, [%4];" \
                 : "=r"(r0), "=r"(r1), "=r"(r2), "=r"(r3) : "r"(addr))

#define LDSM_X4_T(r0, r1, r2, r3, addr) \
    asm volatile("ldmatrix.sync.aligned.m8n8.x4.trans.shared.b16 {%0,%1,%2,%3}, [%4];" \
                 : "=r"(r0), "=r"(r1), "=r"(r2), "=r"(r3) : "r"(addr))

#define MMA_F16(c, a, b0, b1) \
    asm volatile("mma.sync.aligned.m16n8k16.row.col.f32.f16.f16.f32 " \
                 "{%0,%1,%2,%3}, {%4,%5,%6,%7}, {%8,%9}, {%0,%1,%2,%3};" \
                 : "+f"((c)[0]), "+f"((c)[1]), "+f"((c)[2]), "+f"((c)[3]) \
                 : "r"((a)[0]), "r"((a)[1]), "r"((a)[2]), "r"((a)[3]), \
                   "r"(b0), "r"(b1))

#define CP_ASYNC16(dst, src) \
    asm volatile("cp.async.cg.shared.global [%0], [%1], 16;" \
                 :: "r"(dst), "l"(src) : "memory")
#define CP_COMMIT  asm volatile("cp.async.commit_group;" ::: "memory")
#define CP_WAIT0   asm volatile("cp.async.wait_group 0;" ::: "memory")

__device__ __forceinline__ void hsplit_store(__half* hp, __half* lp,
                                             float a, float b) {
    __half ha = __float2half(a), hb = __float2half(b);
    __half2 h; h.x = ha; h.y = hb;
    __half2 l; l.x = __float2half(a - __half2float(ha));
    l.y = __float2half(b - __half2float(hb));
    *(uint32_t*)hp = *(uint32_t*)&h;
    *(uint32_t*)lp = *(uint32_t*)&l;
}

__device__ __forceinline__ float block_sum(float v, float* red) {
    int lane = threadIdx.x & 31, w = threadIdx.x >> 5;
    #pragma unroll
    for (int o = 16; o > 0; o >>= 1) v += __shfl_xor_sync(0xffffffffu, v, o);
    __syncthreads();
    if (lane == 0) red[w] = v;
    __syncthreads();
    if (w == 0) {
        float x = (lane < 8) ? red[lane] : 0.0f;
        #pragma unroll
        for (int o = 4; o > 0; o >>= 1) x += __shfl_xor_sync(0xffffffffu, x, o);
        if (lane == 0) red[0] = x;
    }
    __syncthreads();
    return red[0];
}
__device__ __forceinline__ float gelu_exact(float x) {
    return 0.5f * x * (1.0f + erff(x * 0.7071067811865475f));
}

// -------- weight transpose -> fp16 [Ntot][K], rows [row0, row0+N) --------
__global__ __launch_bounds__(256) void transpose_f16_kernel(
    const float* __restrict__ W, __half* __restrict__ WT,
    int K, int N, int row0, int Ntot)
{
    __shared__ float t[32][33];
    int n0 = blockIdx.x * 32, k0 = blockIdx.y * 32;
    int tx = threadIdx.x & 31, ty = threadIdx.x >> 5;
    #pragma unroll
    for (int i = 0; i < 4; i++)
        t[ty + 8 * i][tx] = W[(size_t)(k0 + ty + 8 * i) * N + n0 + tx];
    __syncthreads();
    #pragma unroll
    for (int i = 0; i < 4; i++)
        WT[(size_t)(row0 + n0 + ty + 8 * i) * K + k0 + tx] =
            __float2half(t[tx][ty + 8 * i]);
}

// -------- plain fp16 split of an fp32 tensor --------
__global__ __launch_bounds__(256) void split_f16_kernel(
    const float* __restrict__ X, __half* __restrict__ Hi, int n)
{
    __half* Lo = Hi + (size_t)n;
    int i = (blockIdx.x * 256 + threadIdx.x) * 4;
    float4 v = *(const float4*)(X + i);
    hsplit_store(Hi + i,     Lo + i,     v.x, v.y);
    hsplit_store(Hi + i + 2, Lo + i + 2, v.z, v.w);
}

// -------- fused embedding + LN1 (fp32 + fp16-split outs) --------
__global__ __launch_bounds__(256) void embed_ln_kernel(
    const int* __restrict__ ids, const float* __restrict__ tok,
    const float* __restrict__ pos, const float* __restrict__ gw,
    const float* __restrict__ bw, float* __restrict__ out,
    __half* __restrict__ Shi)
{
    __shared__ float red[32];
    __half* Slo = Shi + (size_t)MTOK * DM;
    int row = blockIdx.x;
    int s   = row & (SEQ - 1);
    int id  = ids[row];
    int d   = threadIdx.x * 4;
    float4 t4 = *(const float4*)(tok + (size_t)id * DM + d);
    float4 p4 = *(const float4*)(pos + (size_t)s  * DM + d);
    float4 v;
    v.x = t4.x + p4.x; v.y = t4.y + p4.y; v.z = t4.z + p4.z; v.w = t4.w + p4.w;
    float mu = block_sum(v.x + v.y + v.z + v.w, red) * (1.0f / DM);
    float dx = v.x - mu, dy = v.y - mu, dz = v.z - mu, dw = v.w - mu;
    float var = block_sum(dx*dx + dy*dy + dz*dz + dw*dw, red) * (1.0f / DM);
    float rstd = rsqrtf(var + 1e-5f);
    float4 o;
    o.x = dx * rstd * gw[d+0] + bw[d+0];
    o.y = dy * rstd * gw[d+1] + bw[d+1];
    o.z = dz * rstd * gw[d+2] + bw[d+2];
    o.w = dw * rstd * gw[d+3] + bw[d+3];
    size_t off = (size_t)row * DM + d;
    *(float4*)(out + off) = o;
    hsplit_store(Shi + off,     Slo + off,     o.x, o.y);
    hsplit_store(Shi + off + 2, Slo + off + 2, o.z, o.w);
}

// -------- plain LN (fp32 + fp16-split outs) --------
__global__ __launch_bounds__(256) void ln_kernel(
    const float* __restrict__ in, const float* __restrict__ gw,
    const float* __restrict__ bw, float* __restrict__ out,
    __half* __restrict__ Shi)
{
    __shared__ float red[32];
    __half* Slo = Shi + (size_t)MTOK * DM;
    int row = blockIdx.x;
    int d   = threadIdx.x * 4;
    float4 v = *(const float4*)(in + (size_t)row * DM + d);
    float mu = block_sum(v.x + v.y + v.z + v.w, red) * (1.0f / DM);
    float dx = v.x - mu, dy = v.y - mu, dz = v.z - mu, dw = v.w - mu;
    float var = block_sum(dx*dx + dy*dy + dz*dz + dw*dw, red) * (1.0f / DM);
    float rstd = rsqrtf(var + 1e-5f);
    float4 o;
    o.x = dx * rstd * gw[d+0] + bw[d+0];
    o.y = dy * rstd * gw[d+1] + bw[d+1];
    o.z = dz * rstd * gw[d+2] + bw[d+2];
    o.w = dw * rstd * gw[d+3] + bw[d+3];
    size_t off = (size_t)row * DM + d;
    *(float4*)(out + off) = o;
    hsplit_store(Shi + off,     Slo + off,     o.x, o.y);
    hsplit_store(Shi + off + 2, Slo + off + 2, o.z, o.w);
}

// ============================================================
// fp16 asymmetric 2-term GEMM (mma.sync m16n8k16)
// C = A*W + bias.  A: fp16 split [M][K] (lo at +M*K), W: fp16 [N][K].
// acc = A_hi*W + A_lo*W  (error = fp16 quantization of W only)
// epi: 0 fp32 | 1 gelu->fp16split | 2 fp32+R | 3 fp16split
// ============================================================
#define GTILE 10240
#define GBUF  (3 * GTILE)            // A_hi | A_lo | W
#define GEMM_SMEM (2 * GBUF)         // 61440

__global__ __launch_bounds__(256, 2) void gemm_f16_kernel(
    const __half* __restrict__ Ahi, const __half* __restrict__ WT,
    const float* __restrict__ bias, const float* __restrict__ R,
    float* __restrict__ C, int M, int N, int K, int epi)
{
    extern __shared__ char smem[];
    const int tid = threadIdx.x, wid = tid >> 5, lane = tid & 31;
    const int m0 = blockIdx.y * 128, n0 = blockIdx.x * 128;
    const int warpM = (wid & 3) * 32, warpN = (wid >> 2) * 64;
    const uint32_t sb = smem_u32(smem);

    const __half* Alo = Ahi + (size_t)M * K;
    const __half* srcs[3] = {
        Ahi + (size_t)m0 * K, Alo + (size_t)m0 * K, WT + (size_t)n0 * K };

    float acc[2][8][4];
    #pragma unroll
    for (int i = 0; i < 2; i++)
        #pragma unroll
        for (int j = 0; j < 8; j++)
            #pragma unroll
            for (int q = 0; q < 4; q++) acc[i][j][q] = 0.0f;

    const int a_stat = (warpM + ((lane >> 3) & 1) * 8 + (lane & 7)) * 40 + (lane >> 4) * 8;
    const int b_stat = (warpN + ((lane >> 4) & 1) * 8 + (lane & 7)) * 40 + ((lane >> 3) & 1) * 8;
    const int NKB = K >> 5;

#define G_ISSUE(kb, buf) { \
    _Pragma("unroll") for (int i = 0; i < 6; i++) { \
        const int tile = i >> 1; \
        int r = ((tid >> 2) + 64 * (i & 1)) & 127; \
        int s = tid & 3; \
        const __half* src = srcs[tile] + (size_t)r * K + (kb) * 32 + s * 8; \
        uint32_t dst = sb + (buf) * GBUF + tile * GTILE + (uint32_t)(r * 40 + s * 8) * 2; \
        CP_ASYNC16(dst, src); \
    } \
    CP_COMMIT; }

#define G_COMPUTE(buf) { \
    uint32_t tb0 = sb + (buf) * GBUF; \
    _Pragma("unroll") for (int ks = 0; ks < 2; ks++) { \
        const int Cc = ks * 16; \
        uint32_t fa[2][4], fl[2][4]; \
        _Pragma("unroll") for (int mb = 0; mb < 2; mb++) { \
            uint32_t ad = tb0 + (uint32_t)(a_stat + mb * 640 + Cc) * 2; \
            LDSM_X4(fa[mb][0], fa[mb][1], fa[mb][2], fa[mb][3], ad); \
            LDSM_X4(fl[mb][0], fl[mb][1], fl[mb][2], fl[mb][3], ad + GTILE); \
        } \
        _Pragma("unroll") for (int p = 0; p < 4; p++) { \
            uint32_t bw[4]; \
            uint32_t bd = tb0 + 2 * GTILE + (uint32_t)(b_stat + p * 640 + Cc) * 2; \
            LDSM_X4(bw[0], bw[1], bw[2], bw[3], bd); \
            _Pragma("unroll") for (int mb = 0; mb < 2; mb++) { \
                MMA_F16(acc[mb][2*p],   fa[mb], bw[0], bw[1]); \
                MMA_F16(acc[mb][2*p],   fl[mb], bw[0], bw[1]); \
                MMA_F16(acc[mb][2*p+1], fa[mb], bw[2], bw[3]); \
                MMA_F16(acc[mb][2*p+1], fl[mb], bw[2], bw[3]); \
            } } } }

    G_ISSUE(0, 0);
    CP_WAIT0;
    __syncthreads();

    for (int kb = 0; kb < NKB; kb++) {
        if (kb + 1 < NKB) G_ISSUE(kb + 1, (kb + 1) & 1);
        G_COMPUTE(kb & 1);
        if (kb + 1 < NKB) {
            CP_WAIT0;
            __syncthreads();
        }
    }

    // epilogue
    const int g = lane >> 2, t = lane & 3;
    #pragma unroll
    for (int mb = 0; mb < 2; mb++)
        #pragma unroll
        for (int nb = 0; nb < 8; nb++) {
            int row = m0 + warpM + mb * 16 + g;
            int col = n0 + warpN + nb * 8 + 2 * t;
            float2 b2 = *(const float2*)(bias + col);
            float v0 = acc[mb][nb][0] + b2.x, v1 = acc[mb][nb][1] + b2.y;
            float v2 = acc[mb][nb][2] + b2.x, v3 = acc[mb][nb][3] + b2.y;
            size_t o0 = (size_t)row * N + col, o1 = (size_t)(row + 8) * N + col;
            if (epi == 0 || epi == 2) {
                if (epi == 2) {
                    float2 r0 = *(const float2*)(R + o0);
                    float2 r1 = *(const float2*)(R + o1);
                    v0 += r0.x; v1 += r0.y; v2 += r1.x; v3 += r1.y;
                }
                float2 c0 = {v0, v1}, c1 = {v2, v3};
                *(float2*)(C + o0) = c0;
                *(float2*)(C + o1) = c1;
            } else if (epi == 1) {
                v0 = gelu_exact(v0); v1 = gelu_exact(v1);
                v2 = gelu_exact(v2); v3 = gelu_exact(v3);
                __half* Chi = (__half*)C;
                __half* Clo = Chi + (size_t)M * N;
                hsplit_store(Chi + o0, Clo + o0, v0, v1);
                hsplit_store(Chi + o1, Clo + o1, v2, v3);
            } else {
                __half* Chi = (__half*)C;
                __half* Clo = Chi + (size_t)M * N;
                hsplit_store(Chi + o0, Clo + o0, v0, v1);
                hsplit_store(Chi + o1, Clo + o1, v2, v3);
            }
        }
}

// ============================================================
// flash attention, pre-split fp16 Q/K (x3), fp16 V (hi plane)
// strided Q/K/V so tensors can live in fused GEMM outputs
// ============================================================
#define FS 72
#define FK_LO 9216
#define FV    18432
#define FBUF  27648
#define FLASH_SMEM (2 * FBUF + 512)

__global__ __launch_bounds__(128) void flash_mma_kernel(
    const __half* __restrict__ Qhi, int qs,
    const __half* __restrict__ Khi, const __half* __restrict__ Vhi, int ks,
    const int* __restrict__ ids, __half* __restrict__ Ohi, int causal)
{
    extern __shared__ char fsm[];
    const uint32_t sb = smem_u32(fsm);
    float* nadd = (float*)(fsm + 2 * FBUF);

    const int tid = threadIdx.x, wid = tid >> 5, lane = tid & 31;
    const int qt = blockIdx.x, h = blockIdx.y, b = blockIdx.z;
    const int qbase = qt * 64;
    const int g = lane >> 2, t = lane & 3;

    const __half* Qlo = Qhi + (size_t)MTOK * qs;
    const __half* Klo = Khi + (size_t)MTOK * ks;
    __half* Olo = Ohi + (size_t)MTOK * DM;

    const __half* Qph = Qhi + (size_t)b * SEQ * qs + h * DHEAD;
    const __half* Qpl = Qlo + (size_t)b * SEQ * qs + h * DHEAD;
    const __half* Kph = Khi + (size_t)b * SEQ * ks + h * DHEAD;
    const __half* Kpl = Klo + (size_t)b * SEQ * ks + h * DHEAD;
    const __half* Vp  = Vhi + (size_t)b * SEQ * ks + h * DHEAD;

#define F_STAGE(kbase, bufbase, nbuf) { \
    _Pragma("unroll") for (int i = 0; i < 8; i++) { \
        const int arr = i >> 2; \
        int r = (16 * i + (tid >> 3)) & 63; \
        int s = tid & 7; \
        const __half* src = (arr ? Kpl : Kph) + (size_t)((kbase) + r) * ks + s * 8; \
        uint32_t dst = sb + (bufbase) + arr * FK_LO + (uint32_t)(r * FS + s * 8) * 2; \
        CP_ASYNC16(dst, src); \
    } \
    _Pragma("unroll") for (int i = 0; i < 4; i++) { \
        int r = (16 * i + (tid >> 3)) & 63; \
        int s = tid & 7; \
        const __half* src = Vp + (size_t)((kbase) + r) * ks + s * 8; \
        uint32_t dst = sb + (bufbase) + FV + (uint32_t)(r * FS + s * 8) * 2; \
        CP_ASYNC16(dst, src); \
    } \
    if (tid < 64) \
        nadd[(nbuf) * 64 + tid] = (ids[b * SEQ + (kbase) + tid] == 0) ? NEGV : 0.0f; \
    CP_COMMIT; }

    // ---- stage Q into buf1 region, K/V tile 0 into buf0 ----
    #pragma unroll
    for (int i = 0; i < 8; i++) {
        const int arr = i >> 2;
        int r = (16 * i + (tid >> 3)) & 63;
        int s = tid & 7;
        const __half* src = (arr ? Qpl : Qph) + (size_t)(qbase + r) * qs + s * 8;
        uint32_t dst = sb + FBUF + arr * FK_LO + (uint32_t)(r * FS + s * 8) * 2;
        CP_ASYNC16(dst, src);
    }
    CP_COMMIT;
    F_STAGE(0, 0, 0);
    CP_WAIT0;
    __syncthreads();

    // ---- Q fragments from buf1 ----
    uint32_t qh[4][4], ql[4][4];
    {
        int arow = (lane & 15) + 16 * wid;
        int acb  = ((lane >> 4) & 1) * 8;
        #pragma unroll
        for (int kk = 0; kk < 4; kk++) {
            uint32_t ad = sb + FBUF + (uint32_t)(arow * FS + acb + kk * 16) * 2;
            LDSM_X4(qh[kk][0], qh[kk][1], qh[kk][2], qh[kk][3], ad);
            LDSM_X4(ql[kk][0], ql[kk][1], ql[kk][2], ql[kk][3], ad + FK_LO);
        }
    }

    float mA = -3.0e38f, mB = -3.0e38f, lA = 0.0f, lB = 0.0f;
    float O[8][4];
    #pragma unroll
    for (int nb = 0; nb < 8; nb++)
        #pragma unroll
        for (int q = 0; q < 4; q++) O[nb][q] = 0.0f;

    const int rowA = qbase + 16 * wid + g;
    const int nkt = causal ? (qt + 1) : (SEQ / 64);

    for (int kt = 0; kt < nkt; kt++) {
        const int cur = kt & 1;
        const uint32_t cb = sb + cur * FBUF;
        const bool diag = causal && (kt == qt);
        CP_WAIT0;
        __syncthreads();

        // ---- S = Q K^T (fp16x3) ----
        float sc[8][4];
        #pragma unroll
        for (int nb = 0; nb < 8; nb++)
            #pragma unroll
            for (int q = 0; q < 4; q++) sc[nb][q] = 0.0f;

        #pragma unroll
        for (int kk = 0; kk < 4; kk++) {
            #pragma unroll
            for (int p = 0; p < 4; p++) {
                int brow = p * 16 + ((lane >> 4) & 1) * 8 + (lane & 7);
                int bcol = kk * 16 + ((lane >> 3) & 1) * 8;
                uint32_t bd = cb + (uint32_t)(brow * FS + bcol) * 2;
                uint32_t bh[4], bl[4];
                LDSM_X4(bh[0], bh[1], bh[2], bh[3], bd);
                LDSM_X4(bl[0], bl[1], bl[2], bl[3], bd + FK_LO);
                MMA_F16(sc[2*p],   qh[kk], bh[0], bh[1]);
                MMA_F16(sc[2*p],   qh[kk], bl[0], bl[1]);
                MMA_F16(sc[2*p],   ql[kk], bh[0], bh[1]);
                MMA_F16(sc[2*p+1], qh[kk], bh[2], bh[3]);
                MMA_F16(sc[2*p+1], qh[kk], bl[2], bl[3]);
                MMA_F16(sc[2*p+1], ql[kk], bh[2], bh[3]);
            }
        }

        // ---- prefetch next tile (overlaps softmax + PV) ----
        if (kt + 1 < nkt)
            F_STAGE((kt + 1) * 64, (1 - cur) * FBUF, 1 - cur);

        // ---- scale + masks + online softmax ----
        const int kbase = kt * 64;
        float rmaxA = -3.0e38f, rmaxB = -3.0e38f;
        #pragma unroll
        for (int nb = 0; nb < 8; nb++) {
            int col0 = kbase + nb * 8 + 2 * t;
            float p0 = nadd[cur * 64 + nb * 8 + 2 * t];
            float p1 = nadd[cur * 64 + nb * 8 + 2 * t + 1];
            float v0 = sc[nb][0] * 0.125f + p0;
            float v1 = sc[nb][1] * 0.125f + p1;
            float v2 = sc[nb][2] * 0.125f + p0;
            float v3 = sc[nb][3] * 0.125f + p1;
            if (diag) {
                if (col0     > rowA)     v0 += NEGV;
                if (col0 + 1 > rowA)     v1 += NEGV;
                if (col0     > rowA + 8) v2 += NEGV;
                if (col0 + 1 > rowA + 8) v3 += NEGV;
            }
            sc[nb][0] = v0; sc[nb][1] = v1; sc[nb][2] = v2; sc[nb][3] = v3;
            rmaxA = fmaxf(rmaxA, fmaxf(v0, v1));
            rmaxB = fmaxf(rmaxB, fmaxf(v2, v3));
        }
        #pragma unroll
        for (int o = 1; o <= 2; o <<= 1) {
            rmaxA = fmaxf(rmaxA, __shfl_xor_sync(0xffffffffu, rmaxA, o));
            rmaxB = fmaxf(rmaxB, __shfl_xor_sync(0xffffffffu, rmaxB, o));
        }
        float mnA = fmaxf(mA, rmaxA), mnB = fmaxf(mB, rmaxB);
        float aA = __expf(mA - mnA), aB = __expf(mB - mnB);
        mA = mnA; mB = mnB;

        uint32_t af[4][4];
        float sA = 0.0f, sB = 0.0f;
        #pragma unroll
        for (int nb = 0; nb < 8; nb++) {
            float p0 = __expf(sc[nb][0] - mnA);
            float p1 = __expf(sc[nb][1] - mnA);
            float p2 = __expf(sc[nb][2] - mnB);
            float p3 = __expf(sc[nb][3] - mnB);
            __half h0 = __float2half(p0), h1 = __float2half(p1);
            __half h2 = __float2half(p2), h3 = __float2half(p3);
            sA += __half2float(h0) + __half2float(h1);
            sB += __half2float(h2) + __half2float(h3);
            __half2 u01; u01.x = h0; u01.y = h1;
            __half2 u23; u23.x = h2; u23.y = h3;
            int kk = nb >> 1, hi = nb & 1;
            af[kk][hi * 2 + 0] = *(uint32_t*)&u01;
            af[kk][hi * 2 + 1] = *(uint32_t*)&u23;
        }
        #pragma unroll
        for (int o = 1; o <= 2; o <<= 1) {
            sA += __shfl_xor_sync(0xffffffffu, sA, o);
            sB += __shfl_xor_sync(0xffffffffu, sB, o);
        }
        lA = lA * aA + sA; lB = lB * aB + sB;
        #pragma unroll
        for (int nb = 0; nb < 8; nb++) {
            O[nb][0] *= aA; O[nb][1] *= aA;
            O[nb][2] *= aB; O[nb][3] *= aB;
        }

        // ---- O += P V ----
        #pragma unroll
        for (int kk = 0; kk < 4; kk++) {
            #pragma unroll
            for (int nbp = 0; nbp < 4; nbp++) {
                int vrow = kk * 16 + (lane & 15);
                int vcol = nbp * 16 + (lane >> 4) * 8;
                uint32_t bd = cb + FV + (uint32_t)(vrow * FS + vcol) * 2;
                uint32_t v0, v1, v2, v3;
                LDSM_X4_T(v0, v1, v2, v3, bd);
                MMA_F16(O[2*nbp],     af[kk], v0, v1);
                MMA_F16(O[2*nbp + 1], af[kk], v2, v3);
            }
        }
    }

    // ---- write out (fp16 split for next GEMM's A) ----
    float iA = 1.0f / lA, iB = 1.0f / lB;
    #pragma unroll
    for (int nb = 0; nb < 8; nb++) {
        int col = h * DHEAD + nb * 8 + 2 * t;
        size_t off0 = ((size_t)b * SEQ + rowA) * DM + col;
        size_t off1 = ((size_t)b * SEQ + rowA + 8) * DM + col;
        hsplit_store(Ohi + off0, Olo + off0, O[nb][0] * iA, O[nb][1] * iA);
        hsplit_store(Ohi + off1, Olo + off1, O[nb][2] * iB, O[nb][3] * iB);
    }
}

// ============================================================
// host pipeline
// ============================================================
extern "C" void kernel_launch(void* const* d_in, const int* in_sizes, int n_in,
                              void* d_out, int out_size)
{
    const float* input_embedding = (const float*)d_in[0];
    const int*   input_ids       = (const int*)  d_in[1];
    const int*   target_ids      = (const int*)  d_in[2];
    const float* tok_emb = (const float*)d_in[3];
    const float* pos_emb = (const float*)d_in[4];
    const float* ln1_g = (const float*)d_in[5],  *ln1_b = (const float*)d_in[6];
    const float* q1_w  = (const float*)d_in[7],  *q1_b  = (const float*)d_in[8];
    const float* k1_w  = (const float*)d_in[9],  *k1_b  = (const float*)d_in[10];
    const float* v1_w  = (const float*)d_in[11], *v1_b  = (const float*)d_in[12];
    const float* out1_w= (const float*)d_in[13], *out1_b= (const float*)d_in[14];
    const float* ln2_g = (const float*)d_in[15], *ln2_b = (const float*)d_in[16];
    const float* q2_w  = (const float*)d_in[17], *q2_b  = (const float*)d_in[18];
    const float* k2_w  = (const float*)d_in[19], *k2_b  = (const float*)d_in[20];
    const float* v2_w  = (const float*)d_in[21], *v2_b  = (const float*)d_in[22];
    const float* out2_w= (const float*)d_in[23], *out2_b= (const float*)d_in[24];
    const float* ln3_g = (const float*)d_in[25], *ln3_b = (const float*)d_in[26];
    const float* mlp_w1= (const float*)d_in[27], *mlp_b1= (const float*)d_in[28];
    const float* mlp_w2= (const float*)d_in[29], *mlp_b2= (const float*)d_in[30];

    float *xln, *xs, *ies, *qb, *qkv, *kv2, *ab, *hb, *rb, *zb, *zs, *tb, *wt, *gbias;
    cudaGetSymbolAddress((void**)&xln, g_xln);
    cudaGetSymbolAddress((void**)&xs,  g_xs);
    cudaGetSymbolAddress((void**)&ies, g_ies);
    cudaGetSymbolAddress((void**)&qb,  g_qb);
    cudaGetSymbolAddress((void**)&qkv, g_qkv);
    cudaGetSymbolAddress((void**)&kv2, g_kv2);
    cudaGetSymbolAddress((void**)&ab,  g_ab);
    cudaGetSymbolAddress((void**)&hb,  g_hb);
    cudaGetSymbolAddress((void**)&rb,  g_rb);
    cudaGetSymbolAddress((void**)&zb,  g_zb);
    cudaGetSymbolAddress((void**)&zs,  g_zs);
    cudaGetSymbolAddress((void**)&tb,  g_tb);
    cudaGetSymbolAddress((void**)&wt,  g_wt);
    cudaGetSymbolAddress((void**)&gbias, g_bias);

    cudaFuncSetAttribute(gemm_f16_kernel,
                         cudaFuncAttributeMaxDynamicSharedMemorySize, GEMM_SMEM);
    cudaFuncSetAttribute(flash_mma_kernel,
                         cudaFuncAttributeMaxDynamicSharedMemorySize, FLASH_SMEM);

    // ---- one-time prep ----
    {
        dim3 g1(DM / 32, DM / 32);
        transpose_f16_kernel<<<g1, 256>>>(q1_w, (__half*)(wt + WT_QKV1), DM, DM, 0,    3 * DM);
        transpose_f16_kernel<<<g1, 256>>>(k1_w, (__half*)(wt + WT_QKV1), DM, DM, 1024, 3 * DM);
        transpose_f16_kernel<<<g1, 256>>>(v1_w, (__half*)(wt + WT_QKV1), DM, DM, 2048, 3 * DM);
        transpose_f16_kernel<<<g1, 256>>>(out1_w,(__half*)(wt + WT_O1),  DM, DM, 0, DM);
        transpose_f16_kernel<<<g1, 256>>>(q2_w, (__half*)(wt + WT_Q2),   DM, DM, 0, DM);
        transpose_f16_kernel<<<g1, 256>>>(k2_w, (__half*)(wt + WT_KV2),  DM, DM, 0,    2 * DM);
        transpose_f16_kernel<<<g1, 256>>>(v2_w, (__half*)(wt + WT_KV2),  DM, DM, 1024, 2 * DM);
        transpose_f16_kernel<<<g1, 256>>>(out2_w,(__half*)(wt + WT_O2),  DM, DM, 0, DM);
        dim3 gm1(4 * DM / 32, DM / 32);
        transpose_f16_kernel<<<gm1, 256>>>(mlp_w1, (__half*)(wt + WT_M1), DM, 4 * DM, 0, 4 * DM);
        dim3 gm2(DM / 32, 4 * DM / 32);
        transpose_f16_kernel<<<gm2, 256>>>(mlp_w2, (__half*)(wt + WT_M2), 4 * DM, DM, 0, DM);
        split_f16_kernel<<<MTOK * DM / 1024, 256>>>(input_embedding,
                                                    (__half*)ies, MTOK * DM);
        cudaMemcpyAsync(gbias,        q1_b, DM * 4, cudaMemcpyDeviceToDevice);
        cudaMemcpyAsync(gbias + 1024, k1_b, DM * 4, cudaMemcpyDeviceToDevice);
        cudaMemcpyAsync(gbias + 2048, v1_b, DM * 4, cudaMemcpyDeviceToDevice);
        cudaMemcpyAsync(gbias + 4096, k2_b, DM * 4, cudaMemcpyDeviceToDevice);
        cudaMemcpyAsync(gbias + 5120, v2_b, DM * 4, cudaMemcpyDeviceToDevice);
    }

    dim3 gN1(DM / 128, MTOK / 128);          // (8, 32)
    dim3 gN3(3 * DM / 128, MTOK / 128);      // (24, 32) fused QKV
    dim3 gN2(2 * DM / 128, MTOK / 128);      // (16, 32) fused KV2
    dim3 gN4(4 * DM / 128, MTOK / 128);      // (32, 32)
    dim3 gF(SEQ / 64, NH, BATCH);

    // x = LN1(tok_emb[tgt] + pos)
    embed_ln_kernel<<<MTOK, 256>>>(target_ids, tok_emb, pos_emb, ln1_g, ln1_b,
                                   xln, (__half*)xs);

    // self-attention: fused QKV GEMM -> flash -> out-proj
    gemm_f16_kernel<<<gN3, 256, GEMM_SMEM>>>((const __half*)xs,
        (const __half*)(wt + WT_QKV1), gbias, nullptr, qkv, MTOK, 3 * DM, DM, 3);
    flash_mma_kernel<<<gF, 128, FLASH_SMEM>>>((const __half*)qkv, 3 * DM,
        (const __half*)qkv + 1024, (const __half*)qkv + 2048, 3 * DM,
        target_ids, (__half*)ab, 1);
    gemm_f16_kernel<<<gN1, 256, GEMM_SMEM>>>((const __half*)ab,
        (const __half*)(wt + WT_O1), out1_b, xln, hb, MTOK, DM, DM, 2);

    // cross-attention (residual uses LN2 output, matching reference)
    ln_kernel<<<MTOK, 256>>>(hb, ln2_g, ln2_b, zb, (__half*)zs);
    gemm_f16_kernel<<<gN1, 256, GEMM_SMEM>>>((const __half*)zs,
        (const __half*)(wt + WT_Q2), q2_b, nullptr, qb, MTOK, DM, DM, 3);
    gemm_f16_kernel<<<gN2, 256, GEMM_SMEM>>>((const __half*)ies,
        (const __half*)(wt + WT_KV2), gbias + 4096, nullptr, kv2, MTOK, 2 * DM, DM, 3);
    flash_mma_kernel<<<gF, 128, FLASH_SMEM>>>((const __half*)qb, DM,
        (const __half*)kv2, (const __half*)kv2 + 1024, 2 * DM,
        input_ids, (__half*)ab, 0);
    gemm_f16_kernel<<<gN1, 256, GEMM_SMEM>>>((const __half*)ab,
        (const __half*)(wt + WT_O2), out2_b, zb, rb, MTOK, DM, DM, 2);

    // MLP
    ln_kernel<<<MTOK, 256>>>(rb, ln3_g, ln3_b, zb, (__half*)zs);
    gemm_f16_kernel<<<gN4, 256, GEMM_SMEM>>>((const __half*)zs,
        (const __half*)(wt + WT_M1), mlp_b1, nullptr, tb, MTOK, 4 * DM, DM, 1);
    gemm_f16_kernel<<<gN1, 256, GEMM_SMEM>>>((const __half*)tb,
        (const __half*)(wt + WT_M2), mlp_b2, rb, (float*)d_out, MTOK, DM, 4 * DM, 2);
}

// round 14
// speedup vs baseline: 1.3694x; 1.0688x over previous
#include <cuda_runtime.h>
#include <cuda_bf16.h>
#include <cuda_fp16.h>
#include <math.h>
#include <stdint.h>

#define SEQ    2048
#define BATCH  2
#define MTOK   4096      // BATCH*SEQ
#define DM     1024
#define NH     16
#define DHEAD  64
#define NEGV   -1000000000.0f

// -------- scratch (device globals; no allocation allowed) --------
__device__ float g_xln[MTOK * DM];          // LN1 out fp32
__device__ float g_xs [MTOK * DM];          // LN1 out fp16 split
__device__ float g_ies[MTOK * DM];          // input_embedding fp16 split
__device__ float g_qb [MTOK * DM];          // Q2 fp16 split
__device__ float g_qkv[13u << 20];          // fused QKV1 out fp16 split [M][3072]
__device__ float g_kv2[9u << 20];           // fused K2V2 out fp16 split [M][2048]
__device__ float g_ab [MTOK * DM];          // attn out fp16 split
__device__ float g_hb [MTOK * DM];
__device__ float g_rb [MTOK * DM];
__device__ float g_zb [MTOK * DM];          // LN2/LN3 out fp32
__device__ float g_zs [MTOK * DM];          // LN2/LN3 out fp16 split
__device__ float g_tb [MTOK * 4 * DM];      // MLP mid fp16 split
__device__ float g_wt [20u << 20];          // transposed weights fp16 [N][K]
__device__ float g_bias[8192];              // concat biases

#define WT_QKV1 (0u)          // [3072][1024] fp16
#define WT_O1   (2u << 20)
#define WT_Q2   (3u << 20)
#define WT_KV2  (4u << 20)    // [2048][1024]
#define WT_O2   (6u << 20)
#define WT_M1   (7u << 20)    // [4096][1024]
#define WT_M2   (9u << 20)    // [1024][4096]

// ============================================================
// helpers
// ============================================================
__device__ __forceinline__ uint32_t smem_u32(const void* p) {
    uint32_t a;
    asm("{ .reg .u64 t; cvta.to.shared.u64 t, %1; cvt.u32.u64 %0, t; }"
        : "=r"(a) : "l"(p));
    return a;
}

#define LDSM_X4(r0, r1, r2, r3, addr) \
    asm volatile("ldmatrix.sync.aligned.m8n8.x4.shared.b16 {%0,%1,%2,%3}, [%4];" \
                 : "=r"(r0), "=r"(r1), "=r"(r2), "=r"(r3) : "r"(addr))

#define LDSM_X4_T(r0, r1, r2, r3, addr) \
    asm volatile("ldmatrix.sync.aligned.m8n8.x4.trans.shared.b16 {%0,%1,%2,%3}, [%4];" \
                 : "=r"(r0), "=r"(r1), "=r"(r2), "=r"(r3) : "r"(addr))

#define MMA_F16(c, a, b0, b1) \
    asm volatile("mma.sync.aligned.m16n8k16.row.col.f32.f16.f16.f32 " \
                 "{%0,%1,%2,%3}, {%4,%5,%6,%7}, {%8,%9}, {%0,%1,%2,%3};" \
                 : "+f"((c)[0]), "+f"((c)[1]), "+f"((c)[2]), "+f"((c)[3]) \
                 : "r"((a)[0]), "r"((a)[1]), "r"((a)[2]), "r"((a)[3]), \
                   "r"(b0), "r"(b1))

#define CP_ASYNC16(dst, src) \
    asm volatile("cp.async.cg.shared.global [%0], [%1], 16;" \
                 :: "r"(dst), "l"(src) : "memory")
#define CP_COMMIT  asm volatile("cp.async.commit_group;" ::: "memory")
#define CP_WAIT0   asm volatile("cp.async.wait_group 0;" ::: "memory")
#define CP_WAIT1   asm volatile("cp.async.wait_group 1;" ::: "memory")

__device__ __forceinline__ void hsplit_store(__half* hp, __half* lp,
                                             float a, float b) {
    __half ha = __float2half(a), hb = __float2half(b);
    __half2 h; h.x = ha; h.y = hb;
    __half2 l; l.x = __float2half(a - __half2float(ha));
    l.y = __float2half(b - __half2float(hb));
    *(uint32_t*)hp = *(uint32_t*)&h;
    *(uint32_t*)lp = *(uint32_t*)&l;
}

__device__ __forceinline__ float block_sum(float v, float* red) {
    int lane = threadIdx.x & 31, w = threadIdx.x >> 5;
    #pragma unroll
    for (int o = 16; o > 0; o >>= 1) v += __shfl_xor_sync(0xffffffffu, v, o);
    __syncthreads();
    if (lane == 0) red[w] = v;
    __syncthreads();
    if (w == 0) {
        float x = (lane < 8) ? red[lane] : 0.0f;
        #pragma unroll
        for (int o = 4; o > 0; o >>= 1) x += __shfl_xor_sync(0xffffffffu, x, o);
        if (lane == 0) red[0] = x;
    }
    __syncthreads();
    return red[0];
}
__device__ __forceinline__ float gelu_exact(float x) {
    return 0.5f * x * (1.0f + erff(x * 0.7071067811865475f));
}

// ============================================================
// ALL weight transposes in ONE kernel.
// Flat tile grid: 8 x 1024 tiles (1024x1024 weights) + 4096 (mlp_w1)
// + 4096 (mlp_w2) = 16384 blocks of one 32x32 tile each.
// ============================================================
__global__ __launch_bounds__(256) void transpose_all_kernel(
    const float* q1, const float* k1, const float* v1, const float* o1,
    const float* q2, const float* k2, const float* v2, const float* o2,
    const float* m1, const float* m2, float* wtf)
{
    __shared__ float t[32][33];
    int bb = blockIdx.x;
    const float* W; __half* WT; int K, N, row0, Ntot;
    if (bb < 8192) {
        int w = bb >> 10; bb &= 1023;
        K = 1024; N = 1024;
        switch (w) {
            case 0: W = q1; WT = (__half*)(wtf + WT_QKV1); row0 = 0;    Ntot = 3072; break;
            case 1: W = k1; WT = (__half*)(wtf + WT_QKV1); row0 = 1024; Ntot = 3072; break;
            case 2: W = v1; WT = (__half*)(wtf + WT_QKV1); row0 = 2048; Ntot = 3072; break;
            case 3: W = o1; WT = (__half*)(wtf + WT_O1);   row0 = 0;    Ntot = 1024; break;
            case 4: W = q2; WT = (__half*)(wtf + WT_Q2);   row0 = 0;    Ntot = 1024; break;
            case 5: W = k2; WT = (__half*)(wtf + WT_KV2);  row0 = 0;    Ntot = 2048; break;
            case 6: W = v2; WT = (__half*)(wtf + WT_KV2);  row0 = 1024; Ntot = 2048; break;
            default:W = o2; WT = (__half*)(wtf + WT_O2);   row0 = 0;    Ntot = 1024; break;
        }
    } else if (bb < 12288) {
        bb -= 8192;
        W = m1; WT = (__half*)(wtf + WT_M1); K = 1024; N = 4096; row0 = 0; Ntot = 4096;
    } else {
        bb -= 12288;
        W = m2; WT = (__half*)(wtf + WT_M2); K = 4096; N = 1024; row0 = 0; Ntot = 1024;
    }
    int nt = N >> 5;
    int n0 = (bb % nt) * 32, k0 = (bb / nt) * 32;
    int tx = threadIdx.x & 31, ty = threadIdx.x >> 5;
    #pragma unroll
    for (int i = 0; i < 4; i++)
        t[ty + 8 * i][tx] = W[(size_t)(k0 + ty + 8 * i) * N + n0 + tx];
    __syncthreads();
    #pragma unroll
    for (int i = 0; i < 4; i++)
        WT[(size_t)(row0 + n0 + ty + 8 * i) * K + k0 + tx] =
            __float2half(t[tx][ty + 8 * i]);
}

// -------- plain fp16 split of an fp32 tensor --------
__global__ __launch_bounds__(256) void split_f16_kernel(
    const float* __restrict__ X, __half* __restrict__ Hi, int n)
{
    __half* Lo = Hi + (size_t)n;
    int i = (blockIdx.x * 256 + threadIdx.x) * 4;
    float4 v = *(const float4*)(X + i);
    hsplit_store(Hi + i,     Lo + i,     v.x, v.y);
    hsplit_store(Hi + i + 2, Lo + i + 2, v.z, v.w);
}

// -------- fused embedding + LN1 (fp32 + fp16-split outs) --------
__global__ __launch_bounds__(256) void embed_ln_kernel(
    const int* __restrict__ ids, const float* __restrict__ tok,
    const float* __restrict__ pos, const float* __restrict__ gw,
    const float* __restrict__ bw, float* __restrict__ out,
    __half* __restrict__ Shi)
{
    __shared__ float red[32];
    __half* Slo = Shi + (size_t)MTOK * DM;
    int row = blockIdx.x;
    int s   = row & (SEQ - 1);
    int id  = ids[row];
    int d   = threadIdx.x * 4;
    float4 t4 = *(const float4*)(tok + (size_t)id * DM + d);
    float4 p4 = *(const float4*)(pos + (size_t)s  * DM + d);
    float4 v;
    v.x = t4.x + p4.x; v.y = t4.y + p4.y; v.z = t4.z + p4.z; v.w = t4.w + p4.w;
    float mu = block_sum(v.x + v.y + v.z + v.w, red) * (1.0f / DM);
    float dx = v.x - mu, dy = v.y - mu, dz = v.z - mu, dw = v.w - mu;
    float var = block_sum(dx*dx + dy*dy + dz*dz + dw*dw, red) * (1.0f / DM);
    float rstd = rsqrtf(var + 1e-5f);
    float4 o;
    o.x = dx * rstd * gw[d+0] + bw[d+0];
    o.y = dy * rstd * gw[d+1] + bw[d+1];
    o.z = dz * rstd * gw[d+2] + bw[d+2];
    o.w = dw * rstd * gw[d+3] + bw[d+3];
    size_t off = (size_t)row * DM + d;
    *(float4*)(out + off) = o;
    hsplit_store(Shi + off,     Slo + off,     o.x, o.y);
    hsplit_store(Shi + off + 2, Slo + off + 2, o.z, o.w);
}

// -------- plain LN (fp32 + fp16-split outs) --------
__global__ __launch_bounds__(256) void ln_kernel(
    const float* __restrict__ in, const float* __restrict__ gw,
    const float* __restrict__ bw, float* __restrict__ out,
    __half* __restrict__ Shi)
{
    __shared__ float red[32];
    __half* Slo = Shi + (size_t)MTOK * DM;
    int row = blockIdx.x;
    int d   = threadIdx.x * 4;
    float4 v = *(const float4*)(in + (size_t)row * DM + d);
    float mu = block_sum(v.x + v.y + v.z + v.w, red) * (1.0f / DM);
    float dx = v.x - mu, dy = v.y - mu, dz = v.z - mu, dw = v.w - mu;
    float var = block_sum(dx*dx + dy*dy + dz*dz + dw*dw, red) * (1.0f / DM);
    float rstd = rsqrtf(var + 1e-5f);
    float4 o;
    o.x = dx * rstd * gw[d+0] + bw[d+0];
    o.y = dy * rstd * gw[d+1] + bw[d+1];
    o.z = dz * rstd * gw[d+2] + bw[d+2];
    o.w = dw * rstd * gw[d+3] + bw[d+3];
    size_t off = (size_t)row * DM + d;
    *(float4*)(out + off) = o;
    hsplit_store(Shi + off,     Slo + off,     o.x, o.y);
    hsplit_store(Shi + off + 2, Slo + off + 2, o.z, o.w);
}

// ============================================================
// fp16 asymmetric 2-term GEMM, 3-stage cp.async pipeline
// C = A*W + bias.  A: fp16 split [M][K] (lo at +M*K), W: fp16 [N][K].
// epi: 0 fp32 | 1 gelu->fp16split | 2 fp32+R | 3 fp16split
// ============================================================
#define GTILE 10240
#define GBUF  (3 * GTILE)            // A_hi | A_lo | W
#define GEMM_SMEM (3 * GBUF)         // 92160 (3-stage)

__global__ __launch_bounds__(256, 2) void gemm_f16_kernel(
    const __half* __restrict__ Ahi, const __half* __restrict__ WT,
    const float* __restrict__ bias, const float* __restrict__ R,
    float* __restrict__ C, int M, int N, int K, int epi)
{
    extern __shared__ char smem[];
    const int tid = threadIdx.x, wid = tid >> 5, lane = tid & 31;
    const int m0 = blockIdx.y * 128, n0 = blockIdx.x * 128;
    const int warpM = (wid & 3) * 32, warpN = (wid >> 2) * 64;
    const uint32_t sb = smem_u32(smem);

    const __half* Alo = Ahi + (size_t)M * K;
    const __half* srcs[3] = {
        Ahi + (size_t)m0 * K, Alo + (size_t)m0 * K, WT + (size_t)n0 * K };

    float acc[2][8][4];
    #pragma unroll
    for (int i = 0; i < 2; i++)
        #pragma unroll
        for (int j = 0; j < 8; j++)
            #pragma unroll
            for (int q = 0; q < 4; q++) acc[i][j][q] = 0.0f;

    const int a_stat = (warpM + ((lane >> 3) & 1) * 8 + (lane & 7)) * 40 + (lane >> 4) * 8;
    const int b_stat = (warpN + ((lane >> 4) & 1) * 8 + (lane & 7)) * 40 + ((lane >> 3) & 1) * 8;
    const int NKB = K >> 5;

#define G_ISSUE(kb, buf) { \
    _Pragma("unroll") for (int i = 0; i < 6; i++) { \
        const int tile = i >> 1; \
        int r = ((tid >> 2) + 64 * (i & 1)) & 127; \
        int s = tid & 3; \
        const __half* src = srcs[tile] + (size_t)r * K + (kb) * 32 + s * 8; \
        uint32_t dst = sb + (buf) * GBUF + tile * GTILE + (uint32_t)(r * 40 + s * 8) * 2; \
        CP_ASYNC16(dst, src); \
    } \
    CP_COMMIT; }

#define G_COMPUTE(buf) { \
    uint32_t tb0 = sb + (buf) * GBUF; \
    _Pragma("unroll") for (int ks = 0; ks < 2; ks++) { \
        const int Cc = ks * 16; \
        uint32_t fa[2][4], fl[2][4]; \
        _Pragma("unroll") for (int mb = 0; mb < 2; mb++) { \
            uint32_t ad = tb0 + (uint32_t)(a_stat + mb * 640 + Cc) * 2; \
            LDSM_X4(fa[mb][0], fa[mb][1], fa[mb][2], fa[mb][3], ad); \
            LDSM_X4(fl[mb][0], fl[mb][1], fl[mb][2], fl[mb][3], ad + GTILE); \
        } \
        _Pragma("unroll") for (int p = 0; p < 4; p++) { \
            uint32_t bw[4]; \
            uint32_t bd = tb0 + 2 * GTILE + (uint32_t)(b_stat + p * 640 + Cc) * 2; \
            LDSM_X4(bw[0], bw[1], bw[2], bw[3], bd); \
            _Pragma("unroll") for (int mb = 0; mb < 2; mb++) { \
                MMA_F16(acc[mb][2*p],   fa[mb], bw[0], bw[1]); \
                MMA_F16(acc[mb][2*p],   fl[mb], bw[0], bw[1]); \
                MMA_F16(acc[mb][2*p+1], fa[mb], bw[2], bw[3]); \
                MMA_F16(acc[mb][2*p+1], fl[mb], bw[2], bw[3]); \
            } } } }

    // 3-stage pipeline
    G_ISSUE(0, 0);
    G_ISSUE(1, 1);
    int bufc = 0;
    for (int kb = 0; kb < NKB; kb++) {
        if (kb + 1 >= NKB) { CP_WAIT0; } else { CP_WAIT1; }
        __syncthreads();
        int nb2 = kb + 2;
        if (nb2 < NKB) {
            int b2 = nb2 - (nb2 / 3) * 3;
            G_ISSUE(nb2, b2);
        }
        G_COMPUTE(bufc);
        bufc = (bufc == 2) ? 0 : bufc + 1;
    }

    // epilogue
    const int g = lane >> 2, t = lane & 3;
    #pragma unroll
    for (int mb = 0; mb < 2; mb++)
        #pragma unroll
        for (int nb = 0; nb < 8; nb++) {
            int row = m0 + warpM + mb * 16 + g;
            int col = n0 + warpN + nb * 8 + 2 * t;
            float2 b2 = *(const float2*)(bias + col);
            float v0 = acc[mb][nb][0] + b2.x, v1 = acc[mb][nb][1] + b2.y;
            float v2 = acc[mb][nb][2] + b2.x, v3 = acc[mb][nb][3] + b2.y;
            size_t o0 = (size_t)row * N + col, o1 = (size_t)(row + 8) * N + col;
            if (epi == 0 || epi == 2) {
                if (epi == 2) {
                    float2 r0 = *(const float2*)(R + o0);
                    float2 r1 = *(const float2*)(R + o1);
                    v0 += r0.x; v1 += r0.y; v2 += r1.x; v3 += r1.y;
                }
                float2 c0 = {v0, v1}, c1 = {v2, v3};
                *(float2*)(C + o0) = c0;
                *(float2*)(C + o1) = c1;
            } else {
                if (epi == 1) {
                    v0 = gelu_exact(v0); v1 = gelu_exact(v1);
                    v2 = gelu_exact(v2); v3 = gelu_exact(v3);
                }
                __half* Chi = (__half*)C;
                __half* Clo = Chi + (size_t)M * N;
                hsplit_store(Chi + o0, Clo + o0, v0, v1);
                hsplit_store(Chi + o1, Clo + o1, v2, v3);
            }
        }
}

// ============================================================
// flash attention: Q fp16 hi+lo x K fp16 (asymmetric 2-term QK),
// fp16 V; double-buffered K/V cp.async prefetch
// per-buffer: K[64][72] | V[64][72]  (18432 B)
// ============================================================
#define FS 72
#define FV_OFF 9216
#define FBUF   18432
#define FLASH_SMEM (2 * FBUF + 512)

__global__ __launch_bounds__(128) void flash_mma_kernel(
    const __half* __restrict__ Qhi, int qs,
    const __half* __restrict__ Khi, const __half* __restrict__ Vhi, int ks,
    const int* __restrict__ ids, __half* __restrict__ Ohi, int causal)
{
    extern __shared__ char fsm[];
    const uint32_t sb = smem_u32(fsm);
    float* nadd = (float*)(fsm + 2 * FBUF);

    const int tid = threadIdx.x, wid = tid >> 5, lane = tid & 31;
    const int qt = blockIdx.x, h = blockIdx.y, b = blockIdx.z;
    const int qbase = qt * 64;
    const int g = lane >> 2, t = lane & 3;

    const __half* Qlo = Qhi + (size_t)MTOK * qs;
    __half* Olo = Ohi + (size_t)MTOK * DM;

    const __half* Qph = Qhi + (size_t)b * SEQ * qs + h * DHEAD;
    const __half* Qpl = Qlo + (size_t)b * SEQ * qs + h * DHEAD;
    const __half* Kp  = Khi + (size_t)b * SEQ * ks + h * DHEAD;
    const __half* Vp  = Vhi + (size_t)b * SEQ * ks + h * DHEAD;

#define F_STAGE(kbase, bufbase, nbuf) { \
    _Pragma("unroll") for (int i = 0; i < 4; i++) { \
        int r = (16 * i + (tid >> 3)) & 63; \
        int s = tid & 7; \
        const __half* src = Kp + (size_t)((kbase) + r) * ks + s * 8; \
        uint32_t dst = sb + (bufbase) + (uint32_t)(r * FS + s * 8) * 2; \
        CP_ASYNC16(dst, src); \
    } \
    _Pragma("unroll") for (int i = 0; i < 4; i++) { \
        int r = (16 * i + (tid >> 3)) & 63; \
        int s = tid & 7; \
        const __half* src = Vp + (size_t)((kbase) + r) * ks + s * 8; \
        uint32_t dst = sb + (bufbase) + FV_OFF + (uint32_t)(r * FS + s * 8) * 2; \
        CP_ASYNC16(dst, src); \
    } \
    if (tid < 64) \
        nadd[(nbuf) * 64 + tid] = (ids[b * SEQ + (kbase) + tid] == 0) ? NEGV : 0.0f; \
    CP_COMMIT; }

    // ---- stage Q (hi -> buf1 K region, lo -> buf1 V region); K/V tile 0 -> buf0
    #pragma unroll
    for (int i = 0; i < 8; i++) {
        const int arr = i >> 2;
        int r = (16 * i + (tid >> 3)) & 63;
        int s = tid & 7;
        const __half* src = (arr ? Qpl : Qph) + (size_t)(qbase + r) * qs + s * 8;
        uint32_t dst = sb + FBUF + arr * FV_OFF + (uint32_t)(r * FS + s * 8) * 2;
        CP_ASYNC16(dst, src);
    }
    CP_COMMIT;
    F_STAGE(0, 0, 0);
    CP_WAIT0;
    __syncthreads();

    // ---- Q fragments from buf1 ----
    uint32_t qh[4][4], ql[4][4];
    {
        int arow = (lane & 15) + 16 * wid;
        int acb  = ((lane >> 4) & 1) * 8;
        #pragma unroll
        for (int kk = 0; kk < 4; kk++) {
            uint32_t ad = sb + FBUF + (uint32_t)(arow * FS + acb + kk * 16) * 2;
            LDSM_X4(qh[kk][0], qh[kk][1], qh[kk][2], qh[kk][3], ad);
            LDSM_X4(ql[kk][0], ql[kk][1], ql[kk][2], ql[kk][3], ad + FV_OFF);
        }
    }

    float mA = -3.0e38f, mB = -3.0e38f, lA = 0.0f, lB = 0.0f;
    float O[8][4];
    #pragma unroll
    for (int nb = 0; nb < 8; nb++)
        #pragma unroll
        for (int q = 0; q < 4; q++) O[nb][q] = 0.0f;

    const int rowA = qbase + 16 * wid + g;
    const int nkt = causal ? (qt + 1) : (SEQ / 64);

    for (int kt = 0; kt < nkt; kt++) {
        const int cur = kt & 1;
        const uint32_t cb = sb + cur * FBUF;
        const bool diag = causal && (kt == qt);
        CP_WAIT0;
        __syncthreads();

        // ---- S = Q K^T (Q 2-term x K fp16) ----
        float sc[8][4];
        #pragma unroll
        for (int nb = 0; nb < 8; nb++)
            #pragma unroll
            for (int q = 0; q < 4; q++) sc[nb][q] = 0.0f;

        #pragma unroll
        for (int kk = 0; kk < 4; kk++) {
            #pragma unroll
            for (int p = 0; p < 4; p++) {
                int brow = p * 16 + ((lane >> 4) & 1) * 8 + (lane & 7);
                int bcol = kk * 16 + ((lane >> 3) & 1) * 8;
                uint32_t bd = cb + (uint32_t)(brow * FS + bcol) * 2;
                uint32_t bh[4];
                LDSM_X4(bh[0], bh[1], bh[2], bh[3], bd);
                MMA_F16(sc[2*p],   qh[kk], bh[0], bh[1]);
                MMA_F16(sc[2*p],   ql[kk], bh[0], bh[1]);
                MMA_F16(sc[2*p+1], qh[kk], bh[2], bh[3]);
                MMA_F16(sc[2*p+1], ql[kk], bh[2], bh[3]);
            }
        }

        // ---- prefetch next tile (overlaps softmax + PV) ----
        if (kt + 1 < nkt)
            F_STAGE((kt + 1) * 64, (1 - cur) * FBUF, 1 - cur);

        // ---- scale + masks + online softmax ----
        const int kbase = kt * 64;
        float rmaxA = -3.0e38f, rmaxB = -3.0e38f;
        #pragma unroll
        for (int nb = 0; nb < 8; nb++) {
            int col0 = kbase + nb * 8 + 2 * t;
            float p0 = nadd[cur * 64 + nb * 8 + 2 * t];
            float p1 = nadd[cur * 64 + nb * 8 + 2 * t + 1];
            float v0 = sc[nb][0] * 0.125f + p0;
            float v1 = sc[nb][1] * 0.125f + p1;
            float v2 = sc[nb][2] * 0.125f + p0;
            float v3 = sc[nb][3] * 0.125f + p1;
            if (diag) {
                if (col0     > rowA)     v0 += NEGV;
                if (col0 + 1 > rowA)     v1 += NEGV;
                if (col0     > rowA + 8) v2 += NEGV;
                if (col0 + 1 > rowA + 8) v3 += NEGV;
            }
            sc[nb][0] = v0; sc[nb][1] = v1; sc[nb][2] = v2; sc[nb][3] = v3;
            rmaxA = fmaxf(rmaxA, fmaxf(v0, v1));
            rmaxB = fmaxf(rmaxB, fmaxf(v2, v3));
        }
        #pragma unroll
        for (int o = 1; o <= 2; o <<= 1) {
            rmaxA = fmaxf(rmaxA, __shfl_xor_sync(0xffffffffu, rmaxA, o));
            rmaxB = fmaxf(rmaxB, __shfl_xor_sync(0xffffffffu, rmaxB, o));
        }
        float mnA = fmaxf(mA, rmaxA), mnB = fmaxf(mB, rmaxB);
        float aA = __expf(mA - mnA), aB = __expf(mB - mnB);
        mA = mnA; mB = mnB;

        uint32_t af[4][4];
        float sA = 0.0f, sB = 0.0f;
        #pragma unroll
        for (int nb = 0; nb < 8; nb++) {
            float p0 = __expf(sc[nb][0] - mnA);
            float p1 = __expf(sc[nb][1] - mnA);
            float p2 = __expf(sc[nb][2] - mnB);
            float p3 = __expf(sc[nb][3] - mnB);
            __half h0 = __float2half(p0), h1 = __float2half(p1);
            __half h2 = __float2half(p2), h3 = __float2half(p3);
            sA += __half2float(h0) + __half2float(h1);
            sB += __half2float(h2) + __half2float(h3);
            __half2 u01; u01.x = h0; u01.y = h1;
            __half2 u23; u23.x = h2; u23.y = h3;
            int kk = nb >> 1, hi = nb & 1;
            af[kk][hi * 2 + 0] = *(uint32_t*)&u01;
            af[kk][hi * 2 + 1] = *(uint32_t*)&u23;
        }
        #pragma unroll
        for (int o = 1; o <= 2; o <<= 1) {
            sA += __shfl_xor_sync(0xffffffffu, sA, o);
            sB += __shfl_xor_sync(0xffffffffu, sB, o);
        }
        lA = lA * aA + sA; lB = lB * aB + sB;
        #pragma unroll
        for (int nb = 0; nb < 8; nb++) {
            O[nb][0] *= aA; O[nb][1] *= aA;
            O[nb][2] *= aB; O[nb][3] *= aB;
        }

        // ---- O += P V ----
        #pragma unroll
        for (int kk = 0; kk < 4; kk++) {
            #pragma unroll
            for (int nbp = 0; nbp < 4; nbp++) {
                int vrow = kk * 16 + (lane & 15);
                int vcol = nbp * 16 + (lane >> 4) * 8;
                uint32_t bd = cb + FV_OFF + (uint32_t)(vrow * FS + vcol) * 2;
                uint32_t v0, v1, v2, v3;
                LDSM_X4_T(v0, v1, v2, v3, bd);
                MMA_F16(O[2*nbp],     af[kk], v0, v1);
                MMA_F16(O[2*nbp + 1], af[kk], v2, v3);
            }
        }
    }

    // ---- write out (fp16 split for next GEMM's A) ----
    float iA = 1.0f / lA, iB = 1.0f / lB;
    #pragma unroll
    for (int nb = 0; nb < 8; nb++) {
        int col = h * DHEAD + nb * 8 + 2 * t;
        size_t off0 = ((size_t)b * SEQ + rowA) * DM + col;
        size_t off1 = ((size_t)b * SEQ + rowA + 8) * DM + col;
        hsplit_store(Ohi + off0, Olo + off0, O[nb][0] * iA, O[nb][1] * iA);
        hsplit_store(Ohi + off1, Olo + off1, O[nb][2] * iB, O[nb][3] * iB);
    }
}

// ============================================================
// host pipeline
// ============================================================
extern "C" void kernel_launch(void* const* d_in, const int* in_sizes, int n_in,
                              void* d_out, int out_size)
{
    const float* input_embedding = (const float*)d_in[0];
    const int*   input_ids       = (const int*)  d_in[1];
    const int*   target_ids      = (const int*)  d_in[2];
    const float* tok_emb = (const float*)d_in[3];
    const float* pos_emb = (const float*)d_in[4];
    const float* ln1_g = (const float*)d_in[5],  *ln1_b = (const float*)d_in[6];
    const float* q1_w  = (const float*)d_in[7],  *q1_b  = (const float*)d_in[8];
    const float* k1_w  = (const float*)d_in[9],  *k1_b  = (const float*)d_in[10];
    const float* v1_w  = (const float*)d_in[11], *v1_b  = (const float*)d_in[12];
    const float* out1_w= (const float*)d_in[13], *out1_b= (const float*)d_in[14];
    const float* ln2_g = (const float*)d_in[15], *ln2_b = (const float*)d_in[16];
    const float* q2_w  = (const float*)d_in[17], *q2_b  = (const float*)d_in[18];
    const float* k2_w  = (const float*)d_in[19], *k2_b  = (const float*)d_in[20];
    const float* v2_w  = (const float*)d_in[21], *v2_b  = (const float*)d_in[22];
    const float* out2_w= (const float*)d_in[23], *out2_b= (const float*)d_in[24];
    const float* ln3_g = (const float*)d_in[25], *ln3_b = (const float*)d_in[26];
    const float* mlp_w1= (const float*)d_in[27], *mlp_b1= (const float*)d_in[28];
    const float* mlp_w2= (const float*)d_in[29], *mlp_b2= (const float*)d_in[30];

    float *xln, *xs, *ies, *qb, *qkv, *kv2, *ab, *hb, *rb, *zb, *zs, *tb, *wt, *gbias;
    cudaGetSymbolAddress((void**)&xln, g_xln);
    cudaGetSymbolAddress((void**)&xs,  g_xs);
    cudaGetSymbolAddress((void**)&ies, g_ies);
    cudaGetSymbolAddress((void**)&qb,  g_qb);
    cudaGetSymbolAddress((void**)&qkv, g_qkv);
    cudaGetSymbolAddress((void**)&kv2, g_kv2);
    cudaGetSymbolAddress((void**)&ab,  g_ab);
    cudaGetSymbolAddress((void**)&hb,  g_hb);
    cudaGetSymbolAddress((void**)&rb,  g_rb);
    cudaGetSymbolAddress((void**)&zb,  g_zb);
    cudaGetSymbolAddress((void**)&zs,  g_zs);
    cudaGetSymbolAddress((void**)&tb,  g_tb);
    cudaGetSymbolAddress((void**)&wt,  g_wt);
    cudaGetSymbolAddress((void**)&gbias, g_bias);

    cudaFuncSetAttribute(gemm_f16_kernel,
                         cudaFuncAttributeMaxDynamicSharedMemorySize, GEMM_SMEM);
    cudaFuncSetAttribute(flash_mma_kernel,
                         cudaFuncAttributeMaxDynamicSharedMemorySize, FLASH_SMEM);

    // ---- one-time prep: single merged transpose + ies split + biases ----
    transpose_all_kernel<<<16384, 256>>>(q1_w, k1_w, v1_w, out1_w,
                                         q2_w, k2_w, v2_w, out2_w,
                                         mlp_w1, mlp_w2, wt);
    split_f16_kernel<<<MTOK * DM / 1024, 256>>>(input_embedding,
                                                (__half*)ies, MTOK * DM);
    cudaMemcpyAsync(gbias,        q1_b, DM * 4, cudaMemcpyDeviceToDevice);
    cudaMemcpyAsync(gbias + 1024, k1_b, DM * 4, cudaMemcpyDeviceToDevice);
    cudaMemcpyAsync(gbias + 2048, v1_b, DM * 4, cudaMemcpyDeviceToDevice);
    cudaMemcpyAsync(gbias + 4096, k2_b, DM * 4, cudaMemcpyDeviceToDevice);
    cudaMemcpyAsync(gbias + 5120, v2_b, DM * 4, cudaMemcpyDeviceToDevice);

    dim3 gN1(DM / 128, MTOK / 128);          // (8, 32)
    dim3 gN3(3 * DM / 128, MTOK / 128);      // (24, 32) fused QKV
    dim3 gN2(2 * DM / 128, MTOK / 128);      // (16, 32) fused KV2
    dim3 gN4(4 * DM / 128, MTOK / 128);      // (32, 32)
    dim3 gF(SEQ / 64, NH, BATCH);

    // x = LN1(tok_emb[tgt] + pos)
    embed_ln_kernel<<<MTOK, 256>>>(target_ids, tok_emb, pos_emb, ln1_g, ln1_b,
                                   xln, (__half*)xs);

    // self-attention: fused QKV GEMM -> flash -> out-proj
    gemm_f16_kernel<<<gN3, 256, GEMM_SMEM>>>((const __half*)xs,
        (const __half*)(wt + WT_QKV1), gbias, nullptr, qkv, MTOK, 3 * DM, DM, 3);
    flash_mma_kernel<<<gF, 128, FLASH_SMEM>>>((const __half*)qkv, 3 * DM,
        (const __half*)qkv + 1024, (const __half*)qkv + 2048, 3 * DM,
        target_ids, (__half*)ab, 1);
    gemm_f16_kernel<<<gN1, 256, GEMM_SMEM>>>((const __half*)ab,
        (const __half*)(wt + WT_O1), out1_b, xln, hb, MTOK, DM, DM, 2);

    // cross-attention (residual uses LN2 output, matching reference)
    ln_kernel<<<MTOK, 256>>>(hb, ln2_g, ln2_b, zb, (__half*)zs);
    gemm_f16_kernel<<<gN1, 256, GEMM_SMEM>>>((const __half*)zs,
        (const __half*)(wt + WT_Q2), q2_b, nullptr, qb, MTOK, DM, DM, 3);
    gemm_f16_kernel<<<gN2, 256, GEMM_SMEM>>>((const __half*)ies,
        (const __half*)(wt + WT_KV2), gbias + 4096, nullptr, kv2, MTOK, 2 * DM, DM, 3);
    flash_mma_kernel<<<gF, 128, FLASH_SMEM>>>((const __half*)qb, DM,
        (const __half*)kv2, (const __half*)kv2 + 1024, 2 * DM,
        input_ids, (__half*)ab, 0);
    gemm_f16_kernel<<<gN1, 256, GEMM_SMEM>>>((const __half*)ab,
        (const __half*)(wt + WT_O2), out2_b, zb, rb, MTOK, DM, DM, 2);

    // MLP
    ln_kernel<<<MTOK, 256>>>(rb, ln3_g, ln3_b, zb, (__half*)zs);
    gemm_f16_kernel<<<gN4, 256, GEMM_SMEM>>>((const __half*)zs,
        (const __half*)(wt + WT_M1), mlp_b1, nullptr, tb, MTOK, 4 * DM, DM, 1);
    gemm_f16_kernel<<<gN1, 256, GEMM_SMEM>>>((const __half*)tb,
        (const __half*)(wt + WT_M2), mlp_b2, rb, (float*)d_out, MTOK, DM, 4 * DM, 2);
}

// round 15
// speedup vs baseline: 1.3738x; 1.0032x over previous
#include <cuda_runtime.h>
#include <cuda_bf16.h>
#include <cuda_fp16.h>
#include <math.h>
#include <stdint.h>

#define SEQ    2048
#define BATCH  2
#define MTOK   4096      // BATCH*SEQ
#define DM     1024
#define NH     16
#define DHEAD  64
#define NEGV   -1000000000.0f

// -------- scratch (device globals; no allocation allowed) --------
__device__ float g_xln[MTOK * DM];          // LN1 out fp32
__device__ float g_xs [MTOK * DM];          // LN1 out fp16 split
__device__ float g_ies[MTOK * DM];          // input_embedding fp16 split
__device__ float g_qb [MTOK * DM];          // Q2 fp16 split
__device__ float g_qkv[13u << 20];          // fused QKV1 out fp16 split [M][3072]
__device__ float g_kv2[9u << 20];           // fused K2V2 out fp16 split [M][2048]
__device__ float g_ab [MTOK * DM];          // attn out fp16 split
__device__ float g_hb [MTOK * DM];
__device__ float g_rb [MTOK * DM];
__device__ float g_zb [MTOK * DM];          // LN2/LN3 out fp32
__device__ float g_zs [MTOK * DM];          // LN2/LN3 out fp16 split
__device__ float g_tb [MTOK * 4 * DM];      // MLP mid fp16 split
__device__ float g_wt [20u << 20];          // transposed weights fp16 [N][K]
__device__ float g_bias[8192];              // concat biases

#define WT_QKV1 (0u)          // [3072][1024] fp16
#define WT_O1   (2u << 20)
#define WT_Q2   (3u << 20)
#define WT_KV2  (4u << 20)    // [2048][1024]
#define WT_O2   (6u << 20)
#define WT_M1   (7u << 20)    // [4096][1024]
#define WT_M2   (9u << 20)    // [1024][4096]

// ============================================================
// helpers
// ============================================================
__device__ __forceinline__ uint32_t smem_u32(const void* p) {
    uint32_t a;
    asm("{ .reg .u64 t; cvta.to.shared.u64 t, %1; cvt.u32.u64 %0, t; }"
        : "=r"(a) : "l"(p));
    return a;
}

#define LDSM_X4(r0, r1, r2, r3, addr) \
    asm volatile("ldmatrix.sync.aligned.m8n8.x4.shared.b16 {%0,%1,%2,%3}, [%4];" \
                 : "=r"(r0), "=r"(r1), "=r"(r2), "=r"(r3) : "r"(addr))

#define LDSM_X4_T(r0, r1, r2, r3, addr) \
    asm volatile("ldmatrix.sync.aligned.m8n8.x4.trans.shared.b16 {%0,%1,%2,%3}, [%4];" \
                 : "=r"(r0), "=r"(r1), "=r"(r2), "=r"(r3) : "r"(addr))

#define MMA_F16(c, a, b0, b1) \
    asm volatile("mma.sync.aligned.m16n8k16.row.col.f32.f16.f16.f32 " \
                 "{%0,%1,%2,%3}, {%4,%5,%6,%7}, {%8,%9}, {%0,%1,%2,%3};" \
                 : "+f"((c)[0]), "+f"((c)[1]), "+f"((c)[2]), "+f"((c)[3]) \
                 : "r"((a)[0]), "r"((a)[1]), "r"((a)[2]), "r"((a)[3]), \
                   "r"(b0), "r"(b1))

#define CP_ASYNC16(dst, src) \
    asm volatile("cp.async.cg.shared.global [%0], [%1], 16;" \
                 :: "r"(dst), "l"(src) : "memory")
#define CP_COMMIT  asm volatile("cp.async.commit_group;" ::: "memory")
#define CP_WAIT0   asm volatile("cp.async.wait_group 0;" ::: "memory")
#define CP_WAIT1   asm volatile("cp.async.wait_group 1;" ::: "memory")

__device__ __forceinline__ void hsplit_store(__half* hp, __half* lp,
                                             float a, float b) {
    __half ha = __float2half(a), hb = __float2half(b);
    __half2 h; h.x = ha; h.y = hb;
    __half2 l; l.x = __float2half(a - __half2float(ha));
    l.y = __float2half(b - __half2float(hb));
    *(uint32_t*)hp = *(uint32_t*)&h;
    *(uint32_t*)lp = *(uint32_t*)&l;
}

__device__ __forceinline__ float block_sum(float v, float* red) {
    int lane = threadIdx.x & 31, w = threadIdx.x >> 5;
    #pragma unroll
    for (int o = 16; o > 0; o >>= 1) v += __shfl_xor_sync(0xffffffffu, v, o);
    __syncthreads();
    if (lane == 0) red[w] = v;
    __syncthreads();
    if (w == 0) {
        float x = (lane < 8) ? red[lane] : 0.0f;
        #pragma unroll
        for (int o = 4; o > 0; o >>= 1) x += __shfl_xor_sync(0xffffffffu, x, o);
        if (lane == 0) red[0] = x;
    }
    __syncthreads();
    return red[0];
}
__device__ __forceinline__ float gelu_exact(float x) {
    return 0.5f * x * (1.0f + erff(x * 0.7071067811865475f));
}

// ============================================================
// ALL weight transposes in ONE kernel (16384 x 32x32 tiles)
// ============================================================
__global__ __launch_bounds__(256) void transpose_all_kernel(
    const float* q1, const float* k1, const float* v1, const float* o1,
    const float* q2, const float* k2, const float* v2, const float* o2,
    const float* m1, const float* m2, float* wtf)
{
    __shared__ float t[32][33];
    int bb = blockIdx.x;
    const float* W; __half* WT; int K, N, row0;
    if (bb < 8192) {
        int w = bb >> 10; bb &= 1023;
        K = 1024; N = 1024;
        switch (w) {
            case 0: W = q1; WT = (__half*)(wtf + WT_QKV1); row0 = 0;    break;
            case 1: W = k1; WT = (__half*)(wtf + WT_QKV1); row0 = 1024; break;
            case 2: W = v1; WT = (__half*)(wtf + WT_QKV1); row0 = 2048; break;
            case 3: W = o1; WT = (__half*)(wtf + WT_O1);   row0 = 0;    break;
            case 4: W = q2; WT = (__half*)(wtf + WT_Q2);   row0 = 0;    break;
            case 5: W = k2; WT = (__half*)(wtf + WT_KV2);  row0 = 0;    break;
            case 6: W = v2; WT = (__half*)(wtf + WT_KV2);  row0 = 1024; break;
            default:W = o2; WT = (__half*)(wtf + WT_O2);   row0 = 0;    break;
        }
    } else if (bb < 12288) {
        bb -= 8192;
        W = m1; WT = (__half*)(wtf + WT_M1); K = 1024; N = 4096; row0 = 0;
    } else {
        bb -= 12288;
        W = m2; WT = (__half*)(wtf + WT_M2); K = 4096; N = 1024; row0 = 0;
    }
    int nt = N >> 5;
    int n0 = (bb % nt) * 32, k0 = (bb / nt) * 32;
    int tx = threadIdx.x & 31, ty = threadIdx.x >> 5;
    #pragma unroll
    for (int i = 0; i < 4; i++)
        t[ty + 8 * i][tx] = W[(size_t)(k0 + ty + 8 * i) * N + n0 + tx];
    __syncthreads();
    #pragma unroll
    for (int i = 0; i < 4; i++)
        WT[(size_t)(row0 + n0 + ty + 8 * i) * K + k0 + tx] =
            __float2half(t[tx][ty + 8 * i]);
}

// -------- plain fp16 split of an fp32 tensor --------
__global__ __launch_bounds__(256) void split_f16_kernel(
    const float* __restrict__ X, __half* __restrict__ Hi, int n)
{
    __half* Lo = Hi + (size_t)n;
    int i = (blockIdx.x * 256 + threadIdx.x) * 4;
    float4 v = *(const float4*)(X + i);
    hsplit_store(Hi + i,     Lo + i,     v.x, v.y);
    hsplit_store(Hi + i + 2, Lo + i + 2, v.z, v.w);
}

// -------- fused embedding + LN1 (fp32 + fp16-split outs) --------
__global__ __launch_bounds__(256) void embed_ln_kernel(
    const int* __restrict__ ids, const float* __restrict__ tok,
    const float* __restrict__ pos, const float* __restrict__ gw,
    const float* __restrict__ bw, float* __restrict__ out,
    __half* __restrict__ Shi)
{
    __shared__ float red[32];
    __half* Slo = Shi + (size_t)MTOK * DM;
    int row = blockIdx.x;
    int s   = row & (SEQ - 1);
    int id  = ids[row];
    int d   = threadIdx.x * 4;
    float4 t4 = *(const float4*)(tok + (size_t)id * DM + d);
    float4 p4 = *(const float4*)(pos + (size_t)s  * DM + d);
    float4 v;
    v.x = t4.x + p4.x; v.y = t4.y + p4.y; v.z = t4.z + p4.z; v.w = t4.w + p4.w;
    float mu = block_sum(v.x + v.y + v.z + v.w, red) * (1.0f / DM);
    float dx = v.x - mu, dy = v.y - mu, dz = v.z - mu, dw = v.w - mu;
    float var = block_sum(dx*dx + dy*dy + dz*dz + dw*dw, red) * (1.0f / DM);
    float rstd = rsqrtf(var + 1e-5f);
    float4 o;
    o.x = dx * rstd * gw[d+0] + bw[d+0];
    o.y = dy * rstd * gw[d+1] + bw[d+1];
    o.z = dz * rstd * gw[d+2] + bw[d+2];
    o.w = dw * rstd * gw[d+3] + bw[d+3];
    size_t off = (size_t)row * DM + d;
    *(float4*)(out + off) = o;
    hsplit_store(Shi + off,     Slo + off,     o.x, o.y);
    hsplit_store(Shi + off + 2, Slo + off + 2, o.z, o.w);
}

// -------- plain LN (fp32 + fp16-split outs) --------
__global__ __launch_bounds__(256) void ln_kernel(
    const float* __restrict__ in, const float* __restrict__ gw,
    const float* __restrict__ bw, float* __restrict__ out,
    __half* __restrict__ Shi)
{
    __shared__ float red[32];
    __half* Slo = Shi + (size_t)MTOK * DM;
    int row = blockIdx.x;
    int d   = threadIdx.x * 4;
    float4 v = *(const float4*)(in + (size_t)row * DM + d);
    float mu = block_sum(v.x + v.y + v.z + v.w, red) * (1.0f / DM);
    float dx = v.x - mu, dy = v.y - mu, dz = v.z - mu, dw = v.w - mu;
    float var = block_sum(dx*dx + dy*dy + dz*dz + dw*dw, red) * (1.0f / DM);
    float rstd = rsqrtf(var + 1e-5f);
    float4 o;
    o.x = dx * rstd * gw[d+0] + bw[d+0];
    o.y = dy * rstd * gw[d+1] + bw[d+1];
    o.z = dz * rstd * gw[d+2] + bw[d+2];
    o.w = dw * rstd * gw[d+3] + bw[d+3];
    size_t off = (size_t)row * DM + d;
    *(float4*)(out + off) = o;
    hsplit_store(Shi + off,     Slo + off,     o.x, o.y);
    hsplit_store(Shi + off + 2, Slo + off + 2, o.z, o.w);
}

// ============================================================
// fp16 asymmetric 2-term GEMM, 3-stage cp.async pipeline,
// register-double-buffered fragments (LDSM prefetched one step ahead)
// C = A*W + bias.  A: fp16 split [M][K] (lo at +M*K), W: fp16 [N][K].
// epi: 0 fp32 | 1 gelu->fp16split | 2 fp32+R | 3 fp16split
// ============================================================
#define GTILE 10240
#define GBUF  (3 * GTILE)            // A_hi | A_lo | W
#define GEMM_SMEM (3 * GBUF)         // 92160 (3-stage)

__global__ __launch_bounds__(256, 2) void gemm_f16_kernel(
    const __half* __restrict__ Ahi, const __half* __restrict__ WT,
    const float* __restrict__ bias, const float* __restrict__ R,
    float* __restrict__ C, int M, int N, int K, int epi)
{
    extern __shared__ char smem[];
    const int tid = threadIdx.x, wid = tid >> 5, lane = tid & 31;
    const int m0 = blockIdx.y * 128, n0 = blockIdx.x * 128;
    const int warpM = (wid & 3) * 32, warpN = (wid >> 2) * 64;
    const uint32_t sb = smem_u32(smem);

    const __half* Alo = Ahi + (size_t)M * K;
    const __half* srcs[3] = {
        Ahi + (size_t)m0 * K, Alo + (size_t)m0 * K, WT + (size_t)n0 * K };

    float acc[2][8][4];
    #pragma unroll
    for (int i = 0; i < 2; i++)
        #pragma unroll
        for (int j = 0; j < 8; j++)
            #pragma unroll
            for (int q = 0; q < 4; q++) acc[i][j][q] = 0.0f;

    const int a_stat = (warpM + ((lane >> 3) & 1) * 8 + (lane & 7)) * 40 + (lane >> 4) * 8;
    const int b_stat = (warpN + ((lane >> 4) & 1) * 8 + (lane & 7)) * 40 + ((lane >> 3) & 1) * 8;
    const int NKB = K >> 5;

#define G_ISSUE(kb, buf) { \
    _Pragma("unroll") for (int i = 0; i < 6; i++) { \
        const int tile = i >> 1; \
        int r = ((tid >> 2) + 64 * (i & 1)) & 127; \
        int s = tid & 3; \
        const __half* src = srcs[tile] + (size_t)r * K + (kb) * 32 + s * 8; \
        uint32_t dst = sb + (buf) * GBUF + tile * GTILE + (uint32_t)(r * 40 + s * 8) * 2; \
        CP_ASYNC16(dst, src); \
    } \
    CP_COMMIT; }

// register-pipelined compute: fragments for (ks,p)+1 loaded before the
// 8 MMAs that consume (ks,p) — every LDSM covered by ~8 MMAs of latency.
#define G_COMPUTE(buf) { \
    uint32_t tb0 = sb + (buf) * GBUF; \
    uint32_t fac[2][4], flc[2][4], fan[2][4], fln[2][4]; \
    uint32_t bwc[4], bwn[4]; \
    _Pragma("unroll") for (int mb = 0; mb < 2; mb++) { \
        uint32_t ad = tb0 + (uint32_t)(a_stat + mb * 640) * 2; \
        LDSM_X4(fac[mb][0], fac[mb][1], fac[mb][2], fac[mb][3], ad); \
        LDSM_X4(flc[mb][0], flc[mb][1], flc[mb][2], flc[mb][3], ad + GTILE); \
    } \
    { uint32_t bd = tb0 + 2 * GTILE + (uint32_t)(b_stat) * 2; \
      LDSM_X4(bwc[0], bwc[1], bwc[2], bwc[3], bd); } \
    _Pragma("unroll") for (int ks = 0; ks < 2; ks++) { \
        _Pragma("unroll") for (int p = 0; p < 4; p++) { \
            if (p < 3) { \
                uint32_t bd = tb0 + 2 * GTILE + \
                    (uint32_t)(b_stat + (p + 1) * 640 + ks * 16) * 2; \
                LDSM_X4(bwn[0], bwn[1], bwn[2], bwn[3], bd); \
            } else if (ks == 0) { \
                _Pragma("unroll") for (int mb = 0; mb < 2; mb++) { \
                    uint32_t ad = tb0 + (uint32_t)(a_stat + mb * 640 + 16) * 2; \
                    LDSM_X4(fan[mb][0], fan[mb][1], fan[mb][2], fan[mb][3], ad); \
                    LDSM_X4(fln[mb][0], fln[mb][1], fln[mb][2], fln[mb][3], ad + GTILE); \
                } \
                uint32_t bd = tb0 + 2 * GTILE + (uint32_t)(b_stat + 16) * 2; \
                LDSM_X4(bwn[0], bwn[1], bwn[2], bwn[3], bd); \
            } \
            _Pragma("unroll") for (int mb = 0; mb < 2; mb++) { \
                MMA_F16(acc[mb][2*p],   fac[mb], bwc[0], bwc[1]); \
                MMA_F16(acc[mb][2*p],   flc[mb], bwc[0], bwc[1]); \
                MMA_F16(acc[mb][2*p+1], fac[mb], bwc[2], bwc[3]); \
                MMA_F16(acc[mb][2*p+1], flc[mb], bwc[2], bwc[3]); \
            } \
            _Pragma("unroll") for (int q = 0; q < 4; q++) bwc[q] = bwn[q]; \
        } \
        if (ks == 0) { \
            _Pragma("unroll") for (int mb = 0; mb < 2; mb++) \
                _Pragma("unroll") for (int q = 0; q < 4; q++) { \
                    fac[mb][q] = fan[mb][q]; flc[mb][q] = fln[mb][q]; \
                } \
        } \
    } }

    // 3-stage pipeline
    G_ISSUE(0, 0);
    G_ISSUE(1, 1);
    int bufc = 0;
    for (int kb = 0; kb < NKB; kb++) {
        if (kb + 1 >= NKB) { CP_WAIT0; } else { CP_WAIT1; }
        __syncthreads();
        int nb2 = kb + 2;
        if (nb2 < NKB) {
            int b2 = nb2 - (nb2 / 3) * 3;
            G_ISSUE(nb2, b2);
        }
        G_COMPUTE(bufc);
        bufc = (bufc == 2) ? 0 : bufc + 1;
    }

    // epilogue
    const int g = lane >> 2, t = lane & 3;
    #pragma unroll
    for (int mb = 0; mb < 2; mb++)
        #pragma unroll
        for (int nb = 0; nb < 8; nb++) {
            int row = m0 + warpM + mb * 16 + g;
            int col = n0 + warpN + nb * 8 + 2 * t;
            float2 b2 = *(const float2*)(bias + col);
            float v0 = acc[mb][nb][0] + b2.x, v1 = acc[mb][nb][1] + b2.y;
            float v2 = acc[mb][nb][2] + b2.x, v3 = acc[mb][nb][3] + b2.y;
            size_t o0 = (size_t)row * N + col, o1 = (size_t)(row + 8) * N + col;
            if (epi == 0 || epi == 2) {
                if (epi == 2) {
                    float2 r0 = *(const float2*)(R + o0);
                    float2 r1 = *(const float2*)(R + o1);
                    v0 += r0.x; v1 += r0.y; v2 += r1.x; v3 += r1.y;
                }
                float2 c0 = {v0, v1}, c1 = {v2, v3};
                *(float2*)(C + o0) = c0;
                *(float2*)(C + o1) = c1;
            } else {
                if (epi == 1) {
                    v0 = gelu_exact(v0); v1 = gelu_exact(v1);
                    v2 = gelu_exact(v2); v3 = gelu_exact(v3);
                }
                __half* Chi = (__half*)C;
                __half* Clo = Chi + (size_t)M * N;
                hsplit_store(Chi + o0, Clo + o0, v0, v1);
                hsplit_store(Chi + o1, Clo + o1, v2, v3);
            }
        }
}

// ============================================================
// flash attention: Q fp16 hi+lo x K fp16 (asymmetric 2-term QK),
// fp16 V; double-buffered K/V cp.async prefetch
// ============================================================
#define FS 72
#define FV_OFF 9216
#define FBUF   18432
#define FLASH_SMEM (2 * FBUF + 512)

__global__ __launch_bounds__(128) void flash_mma_kernel(
    const __half* __restrict__ Qhi, int qs,
    const __half* __restrict__ Khi, const __half* __restrict__ Vhi, int ks,
    const int* __restrict__ ids, __half* __restrict__ Ohi, int causal)
{
    extern __shared__ char fsm[];
    const uint32_t sb = smem_u32(fsm);
    float* nadd = (float*)(fsm + 2 * FBUF);

    const int tid = threadIdx.x, wid = tid >> 5, lane = tid & 31;
    const int qt = blockIdx.x, h = blockIdx.y, b = blockIdx.z;
    const int qbase = qt * 64;
    const int g = lane >> 2, t = lane & 3;

    const __half* Qlo = Qhi + (size_t)MTOK * qs;
    __half* Olo = Ohi + (size_t)MTOK * DM;

    const __half* Qph = Qhi + (size_t)b * SEQ * qs + h * DHEAD;
    const __half* Qpl = Qlo + (size_t)b * SEQ * qs + h * DHEAD;
    const __half* Kp  = Khi + (size_t)b * SEQ * ks + h * DHEAD;
    const __half* Vp  = Vhi + (size_t)b * SEQ * ks + h * DHEAD;

#define F_STAGE(kbase, bufbase, nbuf) { \
    _Pragma("unroll") for (int i = 0; i < 4; i++) { \
        int r = (16 * i + (tid >> 3)) & 63; \
        int s = tid & 7; \
        const __half* src = Kp + (size_t)((kbase) + r) * ks + s * 8; \
        uint32_t dst = sb + (bufbase) + (uint32_t)(r * FS + s * 8) * 2; \
        CP_ASYNC16(dst, src); \
    } \
    _Pragma("unroll") for (int i = 0; i < 4; i++) { \
        int r = (16 * i + (tid >> 3)) & 63; \
        int s = tid & 7; \
        const __half* src = Vp + (size_t)((kbase) + r) * ks + s * 8; \
        uint32_t dst = sb + (bufbase) + FV_OFF + (uint32_t)(r * FS + s * 8) * 2; \
        CP_ASYNC16(dst, src); \
    } \
    if (tid < 64) \
        nadd[(nbuf) * 64 + tid] = (ids[b * SEQ + (kbase) + tid] == 0) ? NEGV : 0.0f; \
    CP_COMMIT; }

    // ---- stage Q (hi -> buf1 K region, lo -> buf1 V region); K/V tile 0 -> buf0
    #pragma unroll
    for (int i = 0; i < 8; i++) {
        const int arr = i >> 2;
        int r = (16 * i + (tid >> 3)) & 63;
        int s = tid & 7;
        const __half* src = (arr ? Qpl : Qph) + (size_t)(qbase + r) * qs + s * 8;
        uint32_t dst = sb + FBUF + arr * FV_OFF + (uint32_t)(r * FS + s * 8) * 2;
        CP_ASYNC16(dst, src);
    }
    CP_COMMIT;
    F_STAGE(0, 0, 0);
    CP_WAIT0;
    __syncthreads();

    // ---- Q fragments from buf1 ----
    uint32_t qh[4][4], ql[4][4];
    {
        int arow = (lane & 15) + 16 * wid;
        int acb  = ((lane >> 4) & 1) * 8;
        #pragma unroll
        for (int kk = 0; kk < 4; kk++) {
            uint32_t ad = sb + FBUF + (uint32_t)(arow * FS + acb + kk * 16) * 2;
            LDSM_X4(qh[kk][0], qh[kk][1], qh[kk][2], qh[kk][3], ad);
            LDSM_X4(ql[kk][0], ql[kk][1], ql[kk][2], ql[kk][3], ad + FV_OFF);
        }
    }

    float mA = -3.0e38f, mB = -3.0e38f, lA = 0.0f, lB = 0.0f;
    float O[8][4];
    #pragma unroll
    for (int nb = 0; nb < 8; nb++)
        #pragma unroll
        for (int q = 0; q < 4; q++) O[nb][q] = 0.0f;

    const int rowA = qbase + 16 * wid + g;
    const int nkt = causal ? (qt + 1) : (SEQ / 64);

    for (int kt = 0; kt < nkt; kt++) {
        const int cur = kt & 1;
        const uint32_t cb = sb + cur * FBUF;
        const bool diag = causal && (kt == qt);
        CP_WAIT0;
        __syncthreads();

        // ---- S = Q K^T (Q 2-term x K fp16) ----
        float sc[8][4];
        #pragma unroll
        for (int nb = 0; nb < 8; nb++)
            #pragma unroll
            for (int q = 0; q < 4; q++) sc[nb][q] = 0.0f;

        #pragma unroll
        for (int kk = 0; kk < 4; kk++) {
            #pragma unroll
            for (int p = 0; p < 4; p++) {
                int brow = p * 16 + ((lane >> 4) & 1) * 8 + (lane & 7);
                int bcol = kk * 16 + ((lane >> 3) & 1) * 8;
                uint32_t bd = cb + (uint32_t)(brow * FS + bcol) * 2;
                uint32_t bh[4];
                LDSM_X4(bh[0], bh[1], bh[2], bh[3], bd);
                MMA_F16(sc[2*p],   qh[kk], bh[0], bh[1]);
                MMA_F16(sc[2*p],   ql[kk], bh[0], bh[1]);
                MMA_F16(sc[2*p+1], qh[kk], bh[2], bh[3]);
                MMA_F16(sc[2*p+1], ql[kk], bh[2], bh[3]);
            }
        }

        // ---- prefetch next tile (overlaps softmax + PV) ----
        if (kt + 1 < nkt)
            F_STAGE((kt + 1) * 64, (1 - cur) * FBUF, 1 - cur);

        // ---- scale + masks + online softmax ----
        const int kbase = kt * 64;
        float rmaxA = -3.0e38f, rmaxB = -3.0e38f;
        #pragma unroll
        for (int nb = 0; nb < 8; nb++) {
            int col0 = kbase + nb * 8 + 2 * t;
            float p0 = nadd[cur * 64 + nb * 8 + 2 * t];
            float p1 = nadd[cur * 64 + nb * 8 + 2 * t + 1];
            float v0 = sc[nb][0] * 0.125f + p0;
            float v1 = sc[nb][1] * 0.125f + p1;
            float v2 = sc[nb][2] * 0.125f + p0;
            float v3 = sc[nb][3] * 0.125f + p1;
            if (diag) {
                if (col0     > rowA)     v0 += NEGV;
                if (col0 + 1 > rowA)     v1 += NEGV;
                if (col0     > rowA + 8) v2 += NEGV;
                if (col0 + 1 > rowA + 8) v3 += NEGV;
            }
            sc[nb][0] = v0; sc[nb][1] = v1; sc[nb][2] = v2; sc[nb][3] = v3;
            rmaxA = fmaxf(rmaxA, fmaxf(v0, v1));
            rmaxB = fmaxf(rmaxB, fmaxf(v2, v3));
        }
        #pragma unroll
        for (int o = 1; o <= 2; o <<= 1) {
            rmaxA = fmaxf(rmaxA, __shfl_xor_sync(0xffffffffu, rmaxA, o));
            rmaxB = fmaxf(rmaxB, __shfl_xor_sync(0xffffffffu, rmaxB, o));
        }
        float mnA = fmaxf(mA, rmaxA), mnB = fmaxf(mB, rmaxB);
        float aA = __expf(mA - mnA), aB = __expf(mB - mnB);
        mA = mnA; mB = mnB;

        uint32_t af[4][4];
        float sA = 0.0f, sB = 0.0f;
        #pragma unroll
        for (int nb = 0; nb < 8; nb++) {
            float p0 = __expf(sc[nb][0] - mnA);
            float p1 = __expf(sc[nb][1] - mnA);
            float p2 = __expf(sc[nb][2] - mnB);
            float p3 = __expf(sc[nb][3] - mnB);
            __half h0 = __float2half(p0), h1 = __float2half(p1);
            __half h2 = __float2half(p2), h3 = __float2half(p3);
            sA += __half2float(h0) + __half2float(h1);
            sB += __half2float(h2) + __half2float(h3);
            __half2 u01; u01.x = h0; u01.y = h1;
            __half2 u23; u23.x = h2; u23.y = h3;
            int kk = nb >> 1, hi = nb & 1;
            af[kk][hi * 2 + 0] = *(uint32_t*)&u01;
            af[kk][hi * 2 + 1] = *(uint32_t*)&u23;
        }
        #pragma unroll
        for (int o = 1; o <= 2; o <<= 1) {
            sA += __shfl_xor_sync(0xffffffffu, sA, o);
            sB += __shfl_xor_sync(0xffffffffu, sB, o);
        }
        lA = lA * aA + sA; lB = lB * aB + sB;
        #pragma unroll
        for (int nb = 0; nb < 8; nb++) {
            O[nb][0] *= aA; O[nb][1] *= aA;
            O[nb][2] *= aB; O[nb][3] *= aB;
        }

        // ---- O += P V ----
        #pragma unroll
        for (int kk = 0; kk < 4; kk++) {
            #pragma unroll
            for (int nbp = 0; nbp < 4; nbp++) {
                int vrow = kk * 16 + (lane & 15);
                int vcol = nbp * 16 + (lane >> 4) * 8;
                uint32_t bd = cb + FV_OFF + (uint32_t)(vrow * FS + vcol) * 2;
                uint32_t v0, v1, v2, v3;
                LDSM_X4_T(v0, v1, v2, v3, bd);
                MMA_F16(O[2*nbp],     af[kk], v0, v1);
                MMA_F16(O[2*nbp + 1], af[kk], v2, v3);
            }
        }
    }

    // ---- write out (fp16 split for next GEMM's A) ----
    float iA = 1.0f / lA, iB = 1.0f / lB;
    #pragma unroll
    for (int nb = 0; nb < 8; nb++) {
        int col = h * DHEAD + nb * 8 + 2 * t;
        size_t off0 = ((size_t)b * SEQ + rowA) * DM + col;
        size_t off1 = ((size_t)b * SEQ + rowA + 8) * DM + col;
        hsplit_store(Ohi + off0, Olo + off0, O[nb][0] * iA, O[nb][1] * iA);
        hsplit_store(Ohi + off1, Olo + off1, O[nb][2] * iB, O[nb][3] * iB);
    }
}

// ============================================================
// host pipeline
// ============================================================
extern "C" void kernel_launch(void* const* d_in, const int* in_sizes, int n_in,
                              void* d_out, int out_size)
{
    const float* input_embedding = (const float*)d_in[0];
    const int*   input_ids       = (const int*)  d_in[1];
    const int*   target_ids      = (const int*)  d_in[2];
    const float* tok_emb = (const float*)d_in[3];
    const float* pos_emb = (const float*)d_in[4];
    const float* ln1_g = (const float*)d_in[5],  *ln1_b = (const float*)d_in[6];
    const float* q1_w  = (const float*)d_in[7],  *q1_b  = (const float*)d_in[8];
    const float* k1_w  = (const float*)d_in[9],  *k1_b  = (const float*)d_in[10];
    const float* v1_w  = (const float*)d_in[11], *v1_b  = (const float*)d_in[12];
    const float* out1_w= (const float*)d_in[13], *out1_b= (const float*)d_in[14];
    const float* ln2_g = (const float*)d_in[15], *ln2_b = (const float*)d_in[16];
    const float* q2_w  = (const float*)d_in[17], *q2_b  = (const float*)d_in[18];
    const float* k2_w  = (const float*)d_in[19], *k2_b  = (const float*)d_in[20];
    const float* v2_w  = (const float*)d_in[21], *v2_b  = (const float*)d_in[22];
    const float* out2_w= (const float*)d_in[23], *out2_b= (const float*)d_in[24];
    const float* ln3_g = (const float*)d_in[25], *ln3_b = (const float*)d_in[26];
    const float* mlp_w1= (const float*)d_in[27], *mlp_b1= (const float*)d_in[28];
    const float* mlp_w2= (const float*)d_in[29], *mlp_b2= (const float*)d_in[30];

    float *xln, *xs, *ies, *qb, *qkv, *kv2, *ab, *hb, *rb, *zb, *zs, *tb, *wt, *gbias;
    cudaGetSymbolAddress((void**)&xln, g_xln);
    cudaGetSymbolAddress((void**)&xs,  g_xs);
    cudaGetSymbolAddress((void**)&ies, g_ies);
    cudaGetSymbolAddress((void**)&qb,  g_qb);
    cudaGetSymbolAddress((void**)&qkv, g_qkv);
    cudaGetSymbolAddress((void**)&kv2, g_kv2);
    cudaGetSymbolAddress((void**)&ab,  g_ab);
    cudaGetSymbolAddress((void**)&hb,  g_hb);
    cudaGetSymbolAddress((void**)&rb,  g_rb);
    cudaGetSymbolAddress((void**)&zb,  g_zb);
    cudaGetSymbolAddress((void**)&zs,  g_zs);
    cudaGetSymbolAddress((void**)&tb,  g_tb);
    cudaGetSymbolAddress((void**)&wt,  g_wt);
    cudaGetSymbolAddress((void**)&gbias, g_bias);

    cudaFuncSetAttribute(gemm_f16_kernel,
                         cudaFuncAttributeMaxDynamicSharedMemorySize, GEMM_SMEM);
    cudaFuncSetAttribute(flash_mma_kernel,
                         cudaFuncAttributeMaxDynamicSharedMemorySize, FLASH_SMEM);

    // ---- one-time prep: single merged transpose + ies split + biases ----
    transpose_all_kernel<<<16384, 256>>>(q1_w, k1_w, v1_w, out1_w,
                                         q2_w, k2_w, v2_w, out2_w,
                                         mlp_w1, mlp_w2, wt);
    split_f16_kernel<<<MTOK * DM / 1024, 256>>>(input_embedding,
                                                (__half*)ies, MTOK * DM);
    cudaMemcpyAsync(gbias,        q1_b, DM * 4, cudaMemcpyDeviceToDevice);
    cudaMemcpyAsync(gbias + 1024, k1_b, DM * 4, cudaMemcpyDeviceToDevice);
    cudaMemcpyAsync(gbias + 2048, v1_b, DM * 4, cudaMemcpyDeviceToDevice);
    cudaMemcpyAsync(gbias + 4096, k2_b, DM * 4, cudaMemcpyDeviceToDevice);
    cudaMemcpyAsync(gbias + 5120, v2_b, DM * 4, cudaMemcpyDeviceToDevice);

    dim3 gN1(DM / 128, MTOK / 128);          // (8, 32)
    dim3 gN3(3 * DM / 128, MTOK / 128);      // (24, 32) fused QKV
    dim3 gN2(2 * DM / 128, MTOK / 128);      // (16, 32) fused KV2
    dim3 gN4(4 * DM / 128, MTOK / 128);      // (32, 32)
    dim3 gF(SEQ / 64, NH, BATCH);

    // x = LN1(tok_emb[tgt] + pos)
    embed_ln_kernel<<<MTOK, 256>>>(target_ids, tok_emb, pos_emb, ln1_g, ln1_b,
                                   xln, (__half*)xs);

    // self-attention: fused QKV GEMM -> flash -> out-proj
    gemm_f16_kernel<<<gN3, 256, GEMM_SMEM>>>((const __half*)xs,
        (const __half*)(wt + WT_QKV1), gbias, nullptr, qkv, MTOK, 3 * DM, DM, 3);
    flash_mma_kernel<<<gF, 128, FLASH_SMEM>>>((const __half*)qkv, 3 * DM,
        (const __half*)qkv + 1024, (const __half*)qkv + 2048, 3 * DM,
        target_ids, (__half*)ab, 1);
    gemm_f16_kernel<<<gN1, 256, GEMM_SMEM>>>((const __half*)ab,
        (const __half*)(wt + WT_O1), out1_b, xln, hb, MTOK, DM, DM, 2);

    // cross-attention (residual uses LN2 output, matching reference)
    ln_kernel<<<MTOK, 256>>>(hb, ln2_g, ln2_b, zb, (__half*)zs);
    gemm_f16_kernel<<<gN1, 256, GEMM_SMEM>>>((const __half*)zs,
        (const __half*)(wt + WT_Q2), q2_b, nullptr, qb, MTOK, DM, DM, 3);
    gemm_f16_kernel<<<gN2, 256, GEMM_SMEM>>>((const __half*)ies,
        (const __half*)(wt + WT_KV2), gbias + 4096, nullptr, kv2, MTOK, 2 * DM, DM, 3);
    flash_mma_kernel<<<gF, 128, FLASH_SMEM>>>((const __half*)qb, DM,
        (const __half*)kv2, (const __half*)kv2 + 1024, 2 * DM,
        input_ids, (__half*)ab, 0);
    gemm_f16_kernel<<<gN1, 256, GEMM_SMEM>>>((const __half*)ab,
        (const __half*)(wt + WT_O2), out2_b, zb, rb, MTOK, DM, DM, 2);

    // MLP
    ln_kernel<<<MTOK, 256>>>(rb, ln3_g, ln3_b, zb, (__half*)zs);
    gemm_f16_kernel<<<gN4, 256, GEMM_SMEM>>>((const __half*)zs,
        (const __half*)(wt + WT_M1), mlp_b1, nullptr, tb, MTOK, 4 * DM, DM, 1);
    gemm_f16_kernel<<<gN1, 256, GEMM_SMEM>>>((const __half*)tb,
        (const __half*)(wt + WT_M2), mlp_b2, rb, (float*)d_out, MTOK, DM, 4 * DM, 2);
}